// round 13
// baseline (speedup 1.0000x reference)
#include <cuda_runtime.h>
#include <cuda_fp16.h>
#include <math.h>
#include <stdint.h>

// Problem constants
#define BB 4
#define CC 256
#define HH 128
#define WW 128
#define WS 16
#define NWH 8
#define NWW 8
#define NW 64
#define TT 256
#define NTOK (BB*NW*TT)  // 65536
#define NHEAD 8
#define DH 32
#define DFF 1024

// weight offsets in g_w16
#define W_INW 0
#define W_OW  196608
#define W_L1  262144
#define W_L2  524288
#define W_TOT 786432

// ---------------- device scratch (allocation-free: __device__ globals) ----------
// Never pass these names directly as kernel args from host (host shadow + GB300
// ATS silently reads host memory). Resolved via cudaGetSymbolAddress.
// fp16 buffers of INVALID windows are never written (zero/stale); all consumers mask.
__device__ float  g_x  [NTOK*CC];     // fp32 residual spine
__device__ float  g_src[NTOK*CC];
__device__ float  g_pos[NW*TT*CC];
__device__ float  g_valid[BB*NW];
__device__ __half g_xh  [NTOK*CC];
__device__ __half g_xph [NTOK*CC];
__device__ __half g_qkvh[NTOK*768];
__device__ __half g_atth[NTOK*CC];
__device__ __half g_srch[NTOK*CC];
__device__ __half g_yh  [NTOK*CC];
__device__ __half g_ffh [NTOK*DFF];
__device__ __half g_w16 [W_TOT];

// ---------------- fp16 helpers ----------------------------------------------------
__device__ __forceinline__ void h8_to_f8(uint4 u, float4* dst) {
    __half2* h = (__half2*)&u;
    float2 f0 = __half22float2(h[0]), f1 = __half22float2(h[1]);
    float2 f2 = __half22float2(h[2]), f3 = __half22float2(h[3]);
    dst[0] = make_float4(f0.x, f0.y, f1.x, f1.y);
    dst[1] = make_float4(f2.x, f2.y, f3.x, f3.y);
}
__device__ __forceinline__ uint4 f8_to_h8(float4 a, float4 b) {
    uint4 u;
    ((__half2*)&u)[0] = __floats2half2_rn(a.x, a.y);
    ((__half2*)&u)[1] = __floats2half2_rn(a.z, a.w);
    ((__half2*)&u)[2] = __floats2half2_rn(b.x, b.y);
    ((__half2*)&u)[3] = __floats2half2_rn(b.z, b.w);
    return u;
}

// ---------------- all-weights conversion fp32 -> fp16 (one launch) ----------------
__global__ void convertw_all(const float* __restrict__ inw, const float* __restrict__ ow,
                             const float* __restrict__ l1w, const float* __restrict__ l2w,
                             __half* __restrict__ o)
{
    int i = blockIdx.x * 256 + threadIdx.x;   // grid = W_TOT/256
    float v;
    if      (i < W_OW) v = inw[i];
    else if (i < W_L1) v = ow [i - W_OW];
    else if (i < W_L2) v = l1w[i - W_L1];
    else               v = l2w[i - W_L2];
    o[i] = __float2half_rn(v);
}

// ---------------- pos[w,t,c] = glob_pos windowed + relMLP(t,c) (fused) ------------
__global__ void posrel_kernel(const float* __restrict__ gp,
                              const float* __restrict__ w1, const float* __restrict__ b1,
                              const float* __restrict__ w2, const float* __restrict__ b2)
{
    __shared__ float hid[64];
    int wt = blockIdx.x;              // (w,t)
    int w = wt >> 8, t = wt & 255;
    float cy = (float)(t / WS) / (float)(WS - 1);
    float cx = (float)(t % WS) / (float)(WS - 1);
    if (threadIdx.x < 64) {
        float h = cy * w1[threadIdx.x*2+0] + cx * w1[threadIdx.x*2+1] + b1[threadIdx.x];
        hid[threadIdx.x] = fmaxf(h, 0.f);
    }
    __syncthreads();
    int c = threadIdx.x;
    float s = b2[c];
    #pragma unroll 8
    for (int j = 0; j < 64; j++) s += hid[j] * w2[c*64 + j];
    int wy = w >> 3, wx = w & 7, ty = t >> 4, tx = t & 15;
    g_pos[(size_t)wt*CC + c] = gp[(c*HH + wy*WS + ty)*WW + wx*WS + tx] + s;
}

// ---------------- valid[b,w] = maxpool(defe window) > 0 -------------------------
__global__ void valid_kernel(const float* __restrict__ defe)
{
    int bw = blockIdx.x;
    int b = bw / NW, w = bw % NW;
    int t = threadIdx.x;
    int wy = w / NWW, wx = w % NWW, ty = t / WS, tx = t % WS;
    float v = defe[(b*HH + wy*WS + ty)*WW + wx*WS + tx];
    __shared__ float red[256];
    red[t] = v; __syncthreads();
    for (int s = 128; s > 0; s >>= 1) {
        if (t < s) red[t] = fmaxf(red[t], red[t+s]);
        __syncthreads();
    }
    if (t == 0) g_valid[bw] = red[0] > 0.f ? 1.f : 0.f;
}

// ---------------- window partition (tiled transpose), valid windows only ----------
__global__ void partition_kernel(const float* __restrict__ bm)
{
    __shared__ float tile[32][33];
    int xt = blockIdx.x, y = blockIdx.y;
    int b = blockIdx.z >> 3, ct = blockIdx.z & 7;
    int c0 = ct * 32, x0 = xt * 32;
    int wy = y >> 4;
    int wA = wy*8 + (x0 >> 4), wB = wy*8 + ((x0+16) >> 4);
    if (g_valid[b*NW + wA] == 0.f && g_valid[b*NW + wB] == 0.f) return;
    int ci = threadIdx.x >> 5, xi = threadIdx.x & 31;
    #pragma unroll
    for (int p = 0; p < 4; p++) {
        int c = ci + p*8;
        tile[c][xi] = bm[((size_t)(b*CC + c0 + c)*HH + y)*WW + x0 + xi];
    }
    __syncthreads();
    int ty = y & 15;
    #pragma unroll
    for (int p = 0; p < 4; p++) {
        int xj = ci + p*8;
        int x = x0 + xj;
        int w = wy*8 + (x >> 4);
        if (g_valid[b*NW + w] == 0.f) continue;
        int t = ty*16 + (x & 15);
        float v = tile[xi][xj];
        size_t tok = (size_t)(b*NW + w)*TT + t;
        size_t idx = tok*CC + c0 + xi;
        g_x  [idx] = v;
        g_xh [idx] = __float2half_rn(v);
        g_xph[idx] = __float2half_rn(v + g_pos[((size_t)w*TT + t)*CC + c0 + xi]);
    }
}

// ================= FP16 tensor-core GEMM (3-stage cp.async, BK=64) ===============
// Block 128x128, 4 warps (2m x 2n), warp tile 64x64, m16n8k16.f16.f32.
// 96KB smem -> 2 CTAs/SM. Early-exit on invalid window.

__device__ __forceinline__ void mma_f16(float c[4], const uint32_t a[4], const uint32_t b[2]) {
    asm volatile(
        "mma.sync.aligned.m16n8k16.row.col.f32.f16.f16.f32 "
        "{%0,%1,%2,%3}, {%4,%5,%6,%7}, {%8,%9}, {%0,%1,%2,%3};"
        : "+f"(c[0]), "+f"(c[1]), "+f"(c[2]), "+f"(c[3])
        : "r"(a[0]), "r"(a[1]), "r"(a[2]), "r"(a[3]), "r"(b[0]), "r"(b[1]));
}

__device__ __forceinline__ void cp_async16(uint32_t dst, const void* src) {
    asm volatile("cp.async.cg.shared.global [%0], [%1], 16;" :: "r"(dst), "l"(src));
}

__global__ __launch_bounds__(128)
void gemm_f16(const __half* __restrict__ A0, const __half* __restrict__ A1, int mswitch,
              const __half* __restrict__ Wt, const float* __restrict__ bias,
              __half* __restrict__ C, int ldC, int K, int relu,
              const float* __restrict__ vld)
{
    int n0 = blockIdx.y << 7;
    if (vld[n0 >> 8] == 0.f) return;
    extern __shared__ char smc[];
    uint32_t asB = (uint32_t)__cvta_generic_to_shared(smc);
    uint32_t bsB = asB + 3*16384;
    int tid = threadIdx.x;
    int m0 = blockIdx.x << 7;
    const __half* A = (m0 < mswitch) ? A0 : A1;
    int warp = tid >> 5, lane = tid & 31;
    int wm = (warp & 1) << 6;
    int wn = (warp >> 1) << 6;
    int g = lane >> 2, q = lane & 3;

    int srow = tid >> 3;
    int scb  = tid & 7;

    float c[4][8][4] = {};
    int nk = K >> 6;

#define LOAD_STAGE(st, k0)                                                           \
    {                                                                                \
        _Pragma("unroll")                                                            \
        for (int p = 0; p < 8; p++) {                                                \
            int row = (p << 4) + srow;                                               \
            uint32_t sof = (st)*16384u + (row << 7) + ((scb ^ (row & 7)) << 4);      \
            cp_async16(asB + sof, A  + (size_t)(n0 + row) * K + (k0) + (scb << 3));  \
            cp_async16(bsB + sof, Wt + (size_t)(m0 + row) * K + (k0) + (scb << 3));  \
        }                                                                            \
        asm volatile("cp.async.commit_group;");                                      \
    }

    LOAD_STAGE(0, 0)
    if (nk > 1) LOAD_STAGE(1, 64)
    for (int kt = 0; kt < nk; kt++) {
        if (kt + 1 < nk) asm volatile("cp.async.wait_group 1;");
        else             asm volatile("cp.async.wait_group 0;");
        __syncthreads();
        if (kt + 2 < nk) {
            int st = (kt + 2) % 3;
            LOAD_STAGE(st, (kt + 2) << 6)
        }
        int cur = kt % 3;
        const uint32_t* Ac = (const uint32_t*)(smc + cur*16384);
        const uint32_t* Bc = (const uint32_t*)(smc + 3*16384 + cur*16384);
        #pragma unroll
        for (int kk = 0; kk < 4; kk++) {
            int ch0 = kk << 1, ch1 = ch0 + 1;
            uint32_t af[4][4];
            #pragma unroll
            for (int i = 0; i < 4; i++) {
                int r0 = wm + (i << 4) + g, r1 = r0 + 8;
                af[i][0] = Ac[(r0 << 5) + ((ch0 ^ (r0 & 7)) << 2) + q];
                af[i][1] = Ac[(r1 << 5) + ((ch0 ^ (r1 & 7)) << 2) + q];
                af[i][2] = Ac[(r0 << 5) + ((ch1 ^ (r0 & 7)) << 2) + q];
                af[i][3] = Ac[(r1 << 5) + ((ch1 ^ (r1 & 7)) << 2) + q];
            }
            uint32_t bf[8][2];
            #pragma unroll
            for (int j = 0; j < 8; j++) {
                int n = wn + (j << 3) + g;
                bf[j][0] = Bc[(n << 5) + ((ch0 ^ (n & 7)) << 2) + q];
                bf[j][1] = Bc[(n << 5) + ((ch1 ^ (n & 7)) << 2) + q];
            }
            #pragma unroll
            for (int i = 0; i < 4; i++)
                #pragma unroll
                for (int j = 0; j < 8; j++)
                    mma_f16(c[i][j], af[i], bf[j]);
        }
        __syncthreads();
    }
#undef LOAD_STAGE

    #pragma unroll
    for (int i = 0; i < 4; i++) {
        int row = n0 + wm + (i << 4) + g;
        #pragma unroll
        for (int j = 0; j < 8; j++) {
            int col = m0 + wn + (j << 3) + (q << 1);
            float b0 = bias[col], b1 = bias[col+1];
            float v0 = c[i][j][0] + b0, v1 = c[i][j][1] + b1;
            float v2 = c[i][j][2] + b0, v3 = c[i][j][3] + b1;
            if (relu) {
                v0 = fmaxf(v0, 0.f); v1 = fmaxf(v1, 0.f);
                v2 = fmaxf(v2, 0.f); v3 = fmaxf(v3, 0.f);
            }
            *(__half2*)&C[(size_t) row      * ldC + col] = __floats2half2_rn(v0, v1);
            *(__half2*)&C[(size_t)(row + 8) * ldC + col] = __floats2half2_rn(v2, v3);
        }
    }
}

// ---------------- within-window attention (fp16 qkv, fp32 math) -------------------
#define QSC (0.17677669529663687f * 1.4426950408889634f)

__global__ void attn_within_kernel(const __half* __restrict__ qkv, __half* __restrict__ gatt,
                                   const float* __restrict__ vld)
{
    int bw = blockIdx.x;
    if (vld[bw] == 0.f) return;
    __shared__ float4 ks[128*8];
    __shared__ float4 vs[128*8];
    int h = blockIdx.y, t = threadIdx.x;
    size_t base = (size_t)bw * TT;
    float4 qr[8];
    const __half* qp = qkv + (base + t)*768 + h*DH;
    #pragma unroll
    for (int j = 0; j < 4; j++) h8_to_f8(*(const uint4*)(qp + j*8), &qr[j*2]);
    #pragma unroll
    for (int j = 0; j < 8; j++) {
        qr[j].x *= QSC; qr[j].y *= QSC; qr[j].z *= QSC; qr[j].w *= QSC;
    }
    float s = 0.f;
    float4 acc[8] = {};
    for (int ch = 0; ch < 2; ch++) {
        __syncthreads();
        for (int i = threadIdx.x; i < 128*4; i += 256) {
            int r = i >> 2, d = i & 3;
            const __half* rb = qkv + (base + ch*128 + r)*768 + h*DH;
            h8_to_f8(*(const uint4*)(rb + 256 + d*8), &ks[r*8 + d*2]);
            h8_to_f8(*(const uint4*)(rb + 512 + d*8), &vs[r*8 + d*2]);
        }
        __syncthreads();
        for (int i = 0; i < 128; i++) {
            const float4* kp = &ks[i*8];
            float sc = 0.f;
            #pragma unroll
            for (int j = 0; j < 8; j++) {
                float4 k4 = kp[j];
                sc = fmaf(qr[j].x, k4.x, sc); sc = fmaf(qr[j].y, k4.y, sc);
                sc = fmaf(qr[j].z, k4.z, sc); sc = fmaf(qr[j].w, k4.w, sc);
            }
            float e = exp2f(sc);
            s += e;
            const float4* vp = &vs[i*8];
            #pragma unroll
            for (int j = 0; j < 8; j++) {
                float4 v4 = vp[j];
                acc[j].x = fmaf(e, v4.x, acc[j].x); acc[j].y = fmaf(e, v4.y, acc[j].y);
                acc[j].z = fmaf(e, v4.z, acc[j].z); acc[j].w = fmaf(e, v4.w, acc[j].w);
            }
        }
    }
    float inv = s > 0.f ? 1.f / s : 0.f;
    __half* op = gatt + (base + t)*CC + h*DH;
    #pragma unroll
    for (int j = 0; j < 4; j++) {
        float4 a = acc[2*j], b = acc[2*j+1];
        a.x *= inv; a.y *= inv; a.z *= inv; a.w *= inv;
        b.x *= inv; b.y *= inv; b.z *= inv; b.w *= inv;
        *(uint4*)(op + j*8) = f8_to_h8(a, b);
    }
}

// ---------------- cross-window attention (key padding mask) ----------------------
__global__ void attn_cross_kernel(const __half* __restrict__ qkv,
                                  const float* __restrict__ gvalid,
                                  __half* __restrict__ gatt)
{
    __shared__ float4 ks[NW*8];
    __shared__ float4 vs[NW*8];
    __shared__ float mk[NW];
    int bt = blockIdx.x;
    int b = bt / TT, t = bt % TT;
    int h = blockIdx.y;
    int wq = threadIdx.x;
    if (threadIdx.x < NW) mk[threadIdx.x] = gvalid[b*NW + threadIdx.x];
    __syncthreads();
    for (int i = threadIdx.x; i < NW*4; i += 64) {
        int w = i >> 2, d = i & 3;
        if (mk[w] == 0.f) continue;
        const __half* rb = qkv + ((size_t)(b*NW + w)*TT + t)*768 + h*DH;
        h8_to_f8(*(const uint4*)(rb + 256 + d*8), &ks[w*8 + d*2]);
        h8_to_f8(*(const uint4*)(rb + 512 + d*8), &vs[w*8 + d*2]);
    }
    __syncthreads();
    if (mk[wq] == 0.f) return;
    float4 qr[8];
    size_t qtok = (size_t)(b*NW + wq)*TT + t;
    const __half* qp = qkv + qtok*768 + h*DH;
    #pragma unroll
    for (int j = 0; j < 4; j++) h8_to_f8(*(const uint4*)(qp + j*8), &qr[j*2]);
    #pragma unroll
    for (int j = 0; j < 8; j++) {
        qr[j].x *= QSC; qr[j].y *= QSC; qr[j].z *= QSC; qr[j].w *= QSC;
    }
    float s = 0.f;
    float4 acc[8] = {};
    for (int i = 0; i < NW; i++) {
        if (mk[i] == 0.f) continue;
        const float4* kp = &ks[i*8];
        float sc = 0.f;
        #pragma unroll
        for (int j = 0; j < 8; j++) {
            float4 k4 = kp[j];
            sc = fmaf(qr[j].x, k4.x, sc); sc = fmaf(qr[j].y, k4.y, sc);
            sc = fmaf(qr[j].z, k4.z, sc); sc = fmaf(qr[j].w, k4.w, sc);
        }
        float e = exp2f(sc);
        s += e;
        const float4* vp = &vs[i*8];
        #pragma unroll
        for (int j = 0; j < 8; j++) {
            float4 v4 = vp[j];
            acc[j].x = fmaf(e, v4.x, acc[j].x); acc[j].y = fmaf(e, v4.y, acc[j].y);
            acc[j].z = fmaf(e, v4.z, acc[j].z); acc[j].w = fmaf(e, v4.w, acc[j].w);
        }
    }
    float inv = s > 0.f ? 1.f / s : 0.f;
    __half* op = gatt + qtok*CC + h*DH;
    #pragma unroll
    for (int j = 0; j < 4; j++) {
        float4 a = acc[2*j], b = acc[2*j+1];
        a.x *= inv; a.y *= inv; a.z *= inv; a.w *= inv;
        b.x *= inv; b.y *= inv; b.z *= inv; b.w *= inv;
        *(uint4*)(op + j*8) = f8_to_h8(a, b);
    }
}

// ---------------- fused residual + LayerNorm (warp per token) --------------------
// 8 tokens per block = one window slice -> early-exit on invalid window.
__global__ void ln_kernel(const float* __restrict__ a, const __half* __restrict__ r,
                          const float* __restrict__ g, const float* __restrict__ bb,
                          float* __restrict__ out, __half* __restrict__ out_h,
                          __half* __restrict__ out_hp, const float* __restrict__ vld)
{
    if (vld[blockIdx.x >> 5] == 0.f) return;
    int warp = threadIdx.x >> 5, lane = threadIdx.x & 31;
    size_t tok = (size_t)blockIdx.x * 8 + warp;
    size_t base = tok * CC;
    float4 x0 = *(const float4*)(a + base + lane*4);
    float4 x1 = *(const float4*)(a + base + 128 + lane*4);
    uint2 ru0 = *(const uint2*)(r + base + lane*4);
    uint2 ru1 = *(const uint2*)(r + base + 128 + lane*4);
    float2 ra = __half22float2(*(__half2*)&ru0.x), rb2 = __half22float2(*(__half2*)&ru0.y);
    float2 rc = __half22float2(*(__half2*)&ru1.x), rd = __half22float2(*(__half2*)&ru1.y);
    x0.x += ra.x; x0.y += ra.y; x0.z += rb2.x; x0.w += rb2.y;
    x1.x += rc.x; x1.y += rc.y; x1.z += rd.x; x1.w += rd.y;
    float sum = x0.x+x0.y+x0.z+x0.w + x1.x+x1.y+x1.z+x1.w;
    float sq  = x0.x*x0.x+x0.y*x0.y+x0.z*x0.z+x0.w*x0.w
              + x1.x*x1.x+x1.y*x1.y+x1.z*x1.z+x1.w*x1.w;
    #pragma unroll
    for (int o = 16; o > 0; o >>= 1) {
        sum += __shfl_xor_sync(0xffffffffu, sum, o);
        sq  += __shfl_xor_sync(0xffffffffu, sq,  o);
    }
    float mu  = sum * (1.f/CC);
    float var = sq  * (1.f/CC) - mu*mu;
    float inv = rsqrtf(var + 1e-5f);
    float4 g0 = *(const float4*)(g  + lane*4);
    float4 g1 = *(const float4*)(g  + 128 + lane*4);
    float4 b0 = *(const float4*)(bb + lane*4);
    float4 b1 = *(const float4*)(bb + 128 + lane*4);
    float4 o0, o1;
    o0.x = (x0.x-mu)*inv*g0.x + b0.x; o0.y = (x0.y-mu)*inv*g0.y + b0.y;
    o0.z = (x0.z-mu)*inv*g0.z + b0.z; o0.w = (x0.w-mu)*inv*g0.w + b0.w;
    o1.x = (x1.x-mu)*inv*g1.x + b1.x; o1.y = (x1.y-mu)*inv*g1.y + b1.y;
    o1.z = (x1.z-mu)*inv*g1.z + b1.z; o1.w = (x1.w-mu)*inv*g1.w + b1.w;
    *(float4*)(out + base + lane*4)       = o0;
    *(float4*)(out + base + 128 + lane*4) = o1;
    if (out_h) {
        uint2 h0, h1;
        ((__half2*)&h0)[0] = __floats2half2_rn(o0.x, o0.y);
        ((__half2*)&h0)[1] = __floats2half2_rn(o0.z, o0.w);
        ((__half2*)&h1)[0] = __floats2half2_rn(o1.x, o1.y);
        ((__half2*)&h1)[1] = __floats2half2_rn(o1.z, o1.w);
        *(uint2*)(out_h + base + lane*4)       = h0;
        *(uint2*)(out_h + base + 128 + lane*4) = h1;
    }
    if (out_hp) {
        size_t pb = (tok & (NW*TT - 1)) * CC;
        float4 p0 = *(const float4*)(g_pos + pb + lane*4);
        float4 p1 = *(const float4*)(g_pos + pb + 128 + lane*4);
        uint2 h0, h1;
        ((__half2*)&h0)[0] = __floats2half2_rn(o0.x + p0.x, o0.y + p0.y);
        ((__half2*)&h0)[1] = __floats2half2_rn(o0.z + p0.z, o0.w + p0.w);
        ((__half2*)&h1)[0] = __floats2half2_rn(o1.x + p1.x, o1.y + p1.y);
        ((__half2*)&h1)[1] = __floats2half2_rn(o1.z + p1.z, o1.w + p1.w);
        *(uint2*)(out_hp + base + lane*4)       = h0;
        *(uint2*)(out_hp + base + 128 + lane*4) = h1;
    }
}

// ---------------- final scatter (tiled transpose): out = bm + x*valid ------------
__global__ void output_kernel(const float* __restrict__ bm, float* __restrict__ out)
{
    __shared__ float tile[32][33];
    int xt = blockIdx.x, y = blockIdx.y;
    int b = blockIdx.z >> 3, ct = blockIdx.z & 7;
    int c0 = ct * 32, x0 = xt * 32;
    int wy = y >> 4, ty = y & 15;
    int hi = threadIdx.x >> 5, lane = threadIdx.x & 31;
    #pragma unroll
    for (int p = 0; p < 4; p++) {
        int xj = hi + p*8;
        int x = x0 + xj;
        int w = wy*8 + (x >> 4);
        int t = ty*16 + (x & 15);
        float vv = g_valid[b*NW + w];
        tile[xj][lane] = vv == 0.f ? 0.f
            : g_x[((size_t)(b*NW + w)*TT + t)*CC + c0 + lane];
    }
    __syncthreads();
    #pragma unroll
    for (int p = 0; p < 4; p++) {
        int c = hi + p*8;
        size_t idx = ((size_t)(b*CC + c0 + c)*HH + y)*WW + x0 + lane;
        out[idx] = bm[idx] + tile[lane][c];
    }
}

__global__ void valid_out_kernel(float* __restrict__ out)
{
    int i = threadIdx.x;
    out[(size_t)BB*CC*HH*WW + i] = g_valid[i];
}

// =================================================================================
extern "C" void kernel_launch(void* const* d_in, const int* in_sizes, int n_in,
                              void* d_out, int out_size)
{
    float  *p_x, *p_src, *p_valid;
    __half *p_xh, *p_xph, *p_qkvh, *p_atth, *p_srch, *p_yh, *p_ffh, *p_w16;
    cudaGetSymbolAddress((void**)&p_x,    g_x);
    cudaGetSymbolAddress((void**)&p_src,  g_src);
    cudaGetSymbolAddress((void**)&p_valid, g_valid);
    cudaGetSymbolAddress((void**)&p_xh,   g_xh);
    cudaGetSymbolAddress((void**)&p_xph,  g_xph);
    cudaGetSymbolAddress((void**)&p_qkvh, g_qkvh);
    cudaGetSymbolAddress((void**)&p_atth, g_atth);
    cudaGetSymbolAddress((void**)&p_srch, g_srch);
    cudaGetSymbolAddress((void**)&p_yh,   g_yh);
    cudaGetSymbolAddress((void**)&p_ffh,  g_ffh);
    cudaGetSymbolAddress((void**)&p_w16,  g_w16);

    static int smem_set = 0;
    if (!smem_set) {
        cudaFuncSetAttribute(gemm_f16, cudaFuncAttributeMaxDynamicSharedMemorySize, 98304);
        smem_set = 1;
    }

    int sh = (n_in > 2 && in_sizes[2] == 1) ? 0 : -1;
    const float* bm    = (const float*)d_in[0];
    const float* defe  = (const float*)d_in[1];
    const float* gp    = (const float*)d_in[3+sh];
    const float* rw1   = (const float*)d_in[4+sh];
    const float* rb1   = (const float*)d_in[5+sh];
    const float* rw2   = (const float*)d_in[6+sh];
    const float* rb2   = (const float*)d_in[7+sh];
    const float* inw   = (const float*)d_in[8+sh];
    const float* inb   = (const float*)d_in[9+sh];
    const float* ow    = (const float*)d_in[10+sh];
    const float* ob    = (const float*)d_in[11+sh];
    const float* l1w   = (const float*)d_in[12+sh];
    const float* l1b   = (const float*)d_in[13+sh];
    const float* l2w   = (const float*)d_in[14+sh];
    const float* l2b   = (const float*)d_in[15+sh];
    const float* g1    = (const float*)d_in[16+sh];
    const float* b1    = (const float*)d_in[17+sh];
    const float* g2    = (const float*)d_in[18+sh];
    const float* b2    = (const float*)d_in[19+sh];

    // ---- prep ----
    convertw_all<<<W_TOT/256, 256>>>(inw, ow, l1w, l2w, p_w16);
    posrel_kernel<<<NW*TT, 256>>>(gp, rw1, rb1, rw2, rb2);
    valid_kernel<<<BB*NW, 256>>>(defe);
    partition_kernel<<<dim3(4, 128, 32), 256>>>(bm);   // writes x, x_h, xp_h (valid only)

    dim3 gQKV(6, NTOK/128);
    dim3 gOP (2, NTOK/128);
    dim3 gFF1(8, NTOK/128);
    const int GSM = 98304;

    for (int stage = 0; stage < 2; stage++) {
        // fused QKV: Q,K blocks (m0<512) read xp_h; V blocks read x_h
        gemm_f16<<<gQKV, 128, GSM>>>(p_xph, p_xh, 512, p_w16 + W_INW, inb, p_qkvh, 768, CC, 0, p_valid);
        if (stage == 0)
            attn_within_kernel<<<dim3(BB*NW, NHEAD), 256>>>(p_qkvh, p_atth, p_valid);
        else
            attn_cross_kernel<<<dim3(BB*TT, NHEAD), 64>>>(p_qkvh, p_valid, p_atth);
        gemm_f16<<<gOP, 128, GSM>>>(p_atth, p_atth, 0, p_w16 + W_OW, ob, p_yh, CC, CC, 0, p_valid);
        // src = LN(x + y); also emit fp16 src for FFN1
        ln_kernel<<<NTOK/8, 256>>>(p_x, p_yh, g1, b1, p_src, p_srch, (__half*)0, p_valid);
        gemm_f16<<<gFF1, 128, GSM>>>(p_srch, p_srch, 0, p_w16 + W_L1, l1b, p_ffh, DFF, CC, 1, p_valid);
        gemm_f16<<<gOP,  128, GSM>>>(p_ffh,  p_ffh,  0, p_w16 + W_L2, l2b, p_yh,  CC, DFF, 0, p_valid);
        // x = LN(src + ff); stage0 also emits x_h and xp_h for stage1 QKV
        ln_kernel<<<NTOK/8, 256>>>(p_src, p_yh, g2, b2, p_x,
                                   stage == 0 ? p_xh  : (__half*)0,
                                   stage == 0 ? p_xph : (__half*)0, p_valid);
    }

    // ---- output ----
    output_kernel<<<dim3(4, 128, 32), 256>>>(bm, (float*)d_out);
    if (out_size >= BB*CC*HH*WW + BB*NW)
        valid_out_kernel<<<1, BB*NW>>>((float*)d_out);
}

// round 14
// speedup vs baseline: 2.2190x; 2.2190x over previous
#include <cuda_runtime.h>
#include <cuda_fp16.h>
#include <math.h>
#include <stdint.h>

// Problem constants
#define BB 4
#define CC 256
#define HH 128
#define WW 128
#define WS 16
#define NWH 8
#define NWW 8
#define NW 64
#define TT 256
#define NTOK (BB*NW*TT)  // 65536
#define NHEAD 8
#define DH 32
#define DFF 1024

// weight offsets in g_w16
#define W_INW 0
#define W_OW  196608
#define W_L1  262144
#define W_L2  524288
#define W_TOT 786432

// ---------------- device scratch (allocation-free: __device__ globals) ----------
// Never pass these names directly as kernel args from host (host shadow + GB300
// ATS silently reads host memory). Resolved via cudaGetSymbolAddress.
// NOTE: fp16 buffers for INVALID windows are never written (zero from BSS init);
// all consumers of invalid-window data mask it (mk=0 / *valid==0).
__device__ float  g_x  [NTOK*CC];     // fp32 residual spine
__device__ float  g_src[NTOK*CC];
__device__ float  g_pos[NW*TT*CC];
__device__ float  g_rel[TT*CC];
__device__ float  g_valid[BB*NW];
__device__ __half g_xh  [NTOK*CC];    // fp16 GEMM operands
__device__ __half g_xph [NTOK*CC];
__device__ __half g_qkvh[NTOK*768];
__device__ __half g_atth[NTOK*CC];
__device__ __half g_srch[NTOK*CC];
__device__ __half g_yh  [NTOK*CC];
__device__ __half g_ffh [NTOK*DFF];
__device__ __half g_w16 [W_TOT];

// ---------------- fp16 helpers ----------------------------------------------------
__device__ __forceinline__ void h8_to_f8(uint4 u, float4* dst) {
    __half2* h = (__half2*)&u;
    float2 f0 = __half22float2(h[0]), f1 = __half22float2(h[1]);
    float2 f2 = __half22float2(h[2]), f3 = __half22float2(h[3]);
    dst[0] = make_float4(f0.x, f0.y, f1.x, f1.y);
    dst[1] = make_float4(f2.x, f2.y, f3.x, f3.y);
}
__device__ __forceinline__ uint4 f8_to_h8(float4 a, float4 b) {
    uint4 u;
    ((__half2*)&u)[0] = __floats2half2_rn(a.x, a.y);
    ((__half2*)&u)[1] = __floats2half2_rn(a.z, a.w);
    ((__half2*)&u)[2] = __floats2half2_rn(b.x, b.y);
    ((__half2*)&u)[3] = __floats2half2_rn(b.z, b.w);
    return u;
}

// ---------------- weight conversion fp32 -> fp16 -----------------------------------
__global__ void convertw_kernel(const float* __restrict__ w, __half* __restrict__ o, int n)
{
    int i = blockIdx.x * 256 + threadIdx.x;
    if (i < n) o[i] = __float2half_rn(w[i]);
}

// ---------------- rel position MLP ----------------------------------------------
__global__ void rel_kernel(const float* __restrict__ w1, const float* __restrict__ b1,
                           const float* __restrict__ w2, const float* __restrict__ b2)
{
    __shared__ float hid[64];
    int t = blockIdx.x;
    float cy = (float)(t / WS) / (float)(WS - 1);
    float cx = (float)(t % WS) / (float)(WS - 1);
    if (threadIdx.x < 64) {
        float h = cy * w1[threadIdx.x*2+0] + cx * w1[threadIdx.x*2+1] + b1[threadIdx.x];
        hid[threadIdx.x] = fmaxf(h, 0.f);
    }
    __syncthreads();
    int c = threadIdx.x;
    float s = b2[c];
    #pragma unroll 8
    for (int j = 0; j < 64; j++) s += hid[j] * w2[c*64 + j];
    g_rel[t*CC + c] = s;
}

// ---------------- pos[w,t,c] = glob_pos windowed + rel[t,c] ---------------------
__global__ void pos_kernel(const float* __restrict__ gp)
{
    int idx = blockIdx.x * blockDim.x + threadIdx.x;
    if (idx >= NW*TT*CC) return;
    int c = idx % CC;
    int t = (idx / CC) % TT;
    int w = idx / (CC*TT);
    int wy = w / NWW, wx = w % NWW, ty = t / WS, tx = t % WS;
    g_pos[idx] = gp[(c*HH + wy*WS + ty)*WW + wx*WS + tx] + g_rel[t*CC + c];
}

// ---------------- valid[b,w] = maxpool(defe window) > 0 -------------------------
__global__ void valid_kernel(const float* __restrict__ defe)
{
    int bw = blockIdx.x;
    int b = bw / NW, w = bw % NW;
    int t = threadIdx.x;
    int wy = w / NWW, wx = w % NWW, ty = t / WS, tx = t % WS;
    float v = defe[(b*HH + wy*WS + ty)*WW + wx*WS + tx];
    __shared__ float red[256];
    red[t] = v; __syncthreads();
    for (int s = 128; s > 0; s >>= 1) {
        if (t < s) red[t] = fmaxf(red[t], red[t+s]);
        __syncthreads();
    }
    if (t == 0) g_valid[bw] = red[0] > 0.f ? 1.f : 0.f;
}

// ---------------- window partition (tiled transpose), valid windows only ----------
__global__ void partition_kernel(const float* __restrict__ bm)
{
    __shared__ float tile[32][33];
    int xt = blockIdx.x, y = blockIdx.y;
    int b = blockIdx.z >> 3, ct = blockIdx.z & 7;
    int c0 = ct * 32, x0 = xt * 32;
    // this block spans 2 windows in x; skip if both invalid
    int wy = y >> 4;
    int wA = wy*8 + (x0 >> 4), wB = wy*8 + ((x0+16) >> 4);
    if (g_valid[b*NW + wA] == 0.f && g_valid[b*NW + wB] == 0.f) return;
    int ci = threadIdx.x >> 5, xi = threadIdx.x & 31;
    #pragma unroll
    for (int p = 0; p < 4; p++) {
        int c = ci + p*8;
        tile[c][xi] = bm[((size_t)(b*CC + c0 + c)*HH + y)*WW + x0 + xi];
    }
    __syncthreads();
    int ty = y & 15;
    #pragma unroll
    for (int p = 0; p < 4; p++) {
        int xj = ci + p*8;
        int x = x0 + xj;
        int w = wy*8 + (x >> 4);
        if (g_valid[b*NW + w] == 0.f) continue;
        int t = ty*16 + (x & 15);
        float v = tile[xi][xj];
        size_t tok = (size_t)(b*NW + w)*TT + t;
        size_t idx = tok*CC + c0 + xi;
        g_x  [idx] = v;
        g_xh [idx] = __float2half_rn(v);
        g_xph[idx] = __float2half_rn(v + g_pos[((size_t)w*TT + t)*CC + c0 + xi]);
    }
}

// ================= FP16 tensor-core GEMM (3-stage cp.async, BK=64) ===============
// Block 128x128, 4 warps (2m x 2n), warp tile 64x64, m16n8k16.f16.f32.
// Early-exit on invalid window (row-block 128 tokens = half of one window).

__device__ __forceinline__ void mma_f16(float c[4], const uint32_t a[4], const uint32_t b[2]) {
    asm volatile(
        "mma.sync.aligned.m16n8k16.row.col.f32.f16.f16.f32 "
        "{%0,%1,%2,%3}, {%4,%5,%6,%7}, {%8,%9}, {%0,%1,%2,%3};"
        : "+f"(c[0]), "+f"(c[1]), "+f"(c[2]), "+f"(c[3])
        : "r"(a[0]), "r"(a[1]), "r"(a[2]), "r"(a[3]), "r"(b[0]), "r"(b[1]));
}

__device__ __forceinline__ void cp_async16(uint32_t dst, const void* src) {
    asm volatile("cp.async.cg.shared.global [%0], [%1], 16;" :: "r"(dst), "l"(src));
}

__global__ __launch_bounds__(128)
void gemm_f16(const __half* __restrict__ A0, const __half* __restrict__ A1, int mswitch,
              const __half* __restrict__ Wt, const float* __restrict__ bias,
              __half* __restrict__ C, int ldC, int K, int relu,
              const float* __restrict__ vld)
{
    int n0 = blockIdx.y << 7;
    if (vld[n0 >> 8] == 0.f) return;    // whole row-block in an invalid window
    extern __shared__ char smc[];
    uint32_t asB = (uint32_t)__cvta_generic_to_shared(smc);           // A: 3 x 16KB
    uint32_t bsB = asB + 3*16384;                                      // B: 3 x 16KB
    int tid = threadIdx.x;
    int m0 = blockIdx.x << 7;
    const __half* A = (m0 < mswitch) ? A0 : A1;
    int warp = tid >> 5, lane = tid & 31;
    int wm = (warp & 1) << 6;
    int wn = (warp >> 1) << 6;
    int g = lane >> 2, q = lane & 3;

    int srow = tid >> 3;        // 0..15
    int scb  = tid & 7;         // 16B chunk within 128B row

    float c[4][8][4] = {};
    int nk = K >> 6;

#define LOAD_STAGE(st, k0)                                                           \
    {                                                                                \
        _Pragma("unroll")                                                            \
        for (int p = 0; p < 8; p++) {                                                \
            int row = (p << 4) + srow;                                               \
            uint32_t sof = (st)*16384u + (row << 7) + ((scb ^ (row & 7)) << 4);      \
            cp_async16(asB + sof, A  + (size_t)(n0 + row) * K + (k0) + (scb << 3));  \
            cp_async16(bsB + sof, Wt + (size_t)(m0 + row) * K + (k0) + (scb << 3));  \
        }                                                                            \
        asm volatile("cp.async.commit_group;");                                      \
    }

    LOAD_STAGE(0, 0)
    if (nk > 1) LOAD_STAGE(1, 64)
    for (int kt = 0; kt < nk; kt++) {
        if (kt + 1 < nk) asm volatile("cp.async.wait_group 1;");
        else             asm volatile("cp.async.wait_group 0;");
        __syncthreads();
        if (kt + 2 < nk) {
            int st = (kt + 2) % 3;
            LOAD_STAGE(st, (kt + 2) << 6)
        }
        int cur = kt % 3;
        const uint32_t* Ac = (const uint32_t*)(smc + cur*16384);
        const uint32_t* Bc = (const uint32_t*)(smc + 3*16384 + cur*16384);
        #pragma unroll
        for (int kk = 0; kk < 4; kk++) {          // 4 x k16
            int ch0 = kk << 1, ch1 = ch0 + 1;
            uint32_t af[4][4];
            #pragma unroll
            for (int i = 0; i < 4; i++) {
                int r0 = wm + (i << 4) + g, r1 = r0 + 8;
                af[i][0] = Ac[(r0 << 5) + ((ch0 ^ (r0 & 7)) << 2) + q];
                af[i][1] = Ac[(r1 << 5) + ((ch0 ^ (r1 & 7)) << 2) + q];
                af[i][2] = Ac[(r0 << 5) + ((ch1 ^ (r0 & 7)) << 2) + q];
                af[i][3] = Ac[(r1 << 5) + ((ch1 ^ (r1 & 7)) << 2) + q];
            }
            uint32_t bf[8][2];
            #pragma unroll
            for (int j = 0; j < 8; j++) {
                int n = wn + (j << 3) + g;
                bf[j][0] = Bc[(n << 5) + ((ch0 ^ (n & 7)) << 2) + q];
                bf[j][1] = Bc[(n << 5) + ((ch1 ^ (n & 7)) << 2) + q];
            }
            #pragma unroll
            for (int i = 0; i < 4; i++)
                #pragma unroll
                for (int j = 0; j < 8; j++)
                    mma_f16(c[i][j], af[i], bf[j]);
        }
        __syncthreads();
    }
#undef LOAD_STAGE

    #pragma unroll
    for (int i = 0; i < 4; i++) {
        int row = n0 + wm + (i << 4) + g;
        #pragma unroll
        for (int j = 0; j < 8; j++) {
            int col = m0 + wn + (j << 3) + (q << 1);
            float b0 = bias[col], b1 = bias[col+1];
            float v0 = c[i][j][0] + b0, v1 = c[i][j][1] + b1;
            float v2 = c[i][j][2] + b0, v3 = c[i][j][3] + b1;
            if (relu) {
                v0 = fmaxf(v0, 0.f); v1 = fmaxf(v1, 0.f);
                v2 = fmaxf(v2, 0.f); v3 = fmaxf(v3, 0.f);
            }
            *(__half2*)&C[(size_t) row      * ldC + col] = __floats2half2_rn(v0, v1);
            *(__half2*)&C[(size_t)(row + 8) * ldC + col] = __floats2half2_rn(v2, v3);
        }
    }
}

// ---------------- within-window attention (fp16 qkv, fp32 math) -------------------
#define QSC (0.17677669529663687f * 1.4426950408889634f)

__global__ void attn_within_kernel(const __half* __restrict__ qkv, __half* __restrict__ gatt,
                                   const float* __restrict__ vld)
{
    int bw = blockIdx.x;
    if (vld[bw] == 0.f) return;
    __shared__ float4 ks[128*8];
    __shared__ float4 vs[128*8];
    int h = blockIdx.y, t = threadIdx.x;
    size_t base = (size_t)bw * TT;
    float4 qr[8];
    const __half* qp = qkv + (base + t)*768 + h*DH;
    #pragma unroll
    for (int j = 0; j < 4; j++) {
        h8_to_f8(*(const uint4*)(qp + j*8), &qr[j*2]);
    }
    #pragma unroll
    for (int j = 0; j < 8; j++) {
        qr[j].x *= QSC; qr[j].y *= QSC; qr[j].z *= QSC; qr[j].w *= QSC;
    }
    float s = 0.f;
    float4 acc[8] = {};
    for (int ch = 0; ch < 2; ch++) {
        __syncthreads();
        for (int i = threadIdx.x; i < 128*4; i += 256) {
            int r = i >> 2, d = i & 3;
            const __half* rb = qkv + (base + ch*128 + r)*768 + h*DH;
            h8_to_f8(*(const uint4*)(rb + 256 + d*8), &ks[r*8 + d*2]);
            h8_to_f8(*(const uint4*)(rb + 512 + d*8), &vs[r*8 + d*2]);
        }
        __syncthreads();
        for (int i = 0; i < 128; i++) {
            const float4* kp = &ks[i*8];
            float sc = 0.f;
            #pragma unroll
            for (int j = 0; j < 8; j++) {
                float4 k4 = kp[j];
                sc = fmaf(qr[j].x, k4.x, sc); sc = fmaf(qr[j].y, k4.y, sc);
                sc = fmaf(qr[j].z, k4.z, sc); sc = fmaf(qr[j].w, k4.w, sc);
            }
            float e = exp2f(sc);
            s += e;
            const float4* vp = &vs[i*8];
            #pragma unroll
            for (int j = 0; j < 8; j++) {
                float4 v4 = vp[j];
                acc[j].x = fmaf(e, v4.x, acc[j].x); acc[j].y = fmaf(e, v4.y, acc[j].y);
                acc[j].z = fmaf(e, v4.z, acc[j].z); acc[j].w = fmaf(e, v4.w, acc[j].w);
            }
        }
    }
    float inv = s > 0.f ? 1.f / s : 0.f;
    __half* op = gatt + (base + t)*CC + h*DH;
    #pragma unroll
    for (int j = 0; j < 4; j++) {
        float4 a = acc[2*j], b = acc[2*j+1];
        a.x *= inv; a.y *= inv; a.z *= inv; a.w *= inv;
        b.x *= inv; b.y *= inv; b.z *= inv; b.w *= inv;
        *(uint4*)(op + j*8) = f8_to_h8(a, b);
    }
}

// ---------------- cross-window attention (key padding mask) ----------------------
__global__ void attn_cross_kernel(const __half* __restrict__ qkv,
                                  const float* __restrict__ gvalid,
                                  __half* __restrict__ gatt)
{
    __shared__ float4 ks[NW*8];
    __shared__ float4 vs[NW*8];
    __shared__ float mk[NW];
    int bt = blockIdx.x;
    int b = bt / TT, t = bt % TT;
    int h = blockIdx.y;
    int wq = threadIdx.x;
    if (threadIdx.x < NW) mk[threadIdx.x] = gvalid[b*NW + threadIdx.x];
    __syncthreads();
    for (int i = threadIdx.x; i < NW*4; i += 64) {
        int w = i >> 2, d = i & 3;
        if (mk[w] == 0.f) continue;     // invalid window: smem stays stale (masked)
        const __half* rb = qkv + ((size_t)(b*NW + w)*TT + t)*768 + h*DH;
        h8_to_f8(*(const uint4*)(rb + 256 + d*8), &ks[w*8 + d*2]);
        h8_to_f8(*(const uint4*)(rb + 512 + d*8), &vs[w*8 + d*2]);
    }
    __syncthreads();
    if (mk[wq] == 0.f) return;          // query window invalid: output unused
    float4 qr[8];
    size_t qtok = (size_t)(b*NW + wq)*TT + t;
    const __half* qp = qkv + qtok*768 + h*DH;
    #pragma unroll
    for (int j = 0; j < 4; j++) h8_to_f8(*(const uint4*)(qp + j*8), &qr[j*2]);
    #pragma unroll
    for (int j = 0; j < 8; j++) {
        qr[j].x *= QSC; qr[j].y *= QSC; qr[j].z *= QSC; qr[j].w *= QSC;
    }
    float s = 0.f;
    float4 acc[8] = {};
    for (int i = 0; i < NW; i++) {
        if (mk[i] == 0.f) continue;
        const float4* kp = &ks[i*8];
        float sc = 0.f;
        #pragma unroll
        for (int j = 0; j < 8; j++) {
            float4 k4 = kp[j];
            sc = fmaf(qr[j].x, k4.x, sc); sc = fmaf(qr[j].y, k4.y, sc);
            sc = fmaf(qr[j].z, k4.z, sc); sc = fmaf(qr[j].w, k4.w, sc);
        }
        float e = exp2f(sc);
        s += e;
        const float4* vp = &vs[i*8];
        #pragma unroll
        for (int j = 0; j < 8; j++) {
            float4 v4 = vp[j];
            acc[j].x = fmaf(e, v4.x, acc[j].x); acc[j].y = fmaf(e, v4.y, acc[j].y);
            acc[j].z = fmaf(e, v4.z, acc[j].z); acc[j].w = fmaf(e, v4.w, acc[j].w);
        }
    }
    float inv = s > 0.f ? 1.f / s : 0.f;
    __half* op = gatt + qtok*CC + h*DH;
    #pragma unroll
    for (int j = 0; j < 4; j++) {
        float4 a = acc[2*j], b = acc[2*j+1];
        a.x *= inv; a.y *= inv; a.z *= inv; a.w *= inv;
        b.x *= inv; b.y *= inv; b.z *= inv; b.w *= inv;
        *(uint4*)(op + j*8) = f8_to_h8(a, b);
    }
}

// ---------------- fused residual + LayerNorm (warp per token) --------------------
// 8 tokens per block = one window slice -> early-exit on invalid window.
__global__ void ln_kernel(const float* __restrict__ a, const __half* __restrict__ r,
                          const float* __restrict__ g, const float* __restrict__ bb,
                          float* __restrict__ out, __half* __restrict__ out_h,
                          __half* __restrict__ out_hp, const float* __restrict__ vld)
{
    if (vld[blockIdx.x >> 5] == 0.f) return;
    int warp = threadIdx.x >> 5, lane = threadIdx.x & 31;
    size_t tok = (size_t)blockIdx.x * 8 + warp;
    size_t base = tok * CC;
    float4 x0 = *(const float4*)(a + base + lane*4);
    float4 x1 = *(const float4*)(a + base + 128 + lane*4);
    uint2 ru0 = *(const uint2*)(r + base + lane*4);
    uint2 ru1 = *(const uint2*)(r + base + 128 + lane*4);
    float2 ra = __half22float2(*(__half2*)&ru0.x), rb2 = __half22float2(*(__half2*)&ru0.y);
    float2 rc = __half22float2(*(__half2*)&ru1.x), rd = __half22float2(*(__half2*)&ru1.y);
    x0.x += ra.x; x0.y += ra.y; x0.z += rb2.x; x0.w += rb2.y;
    x1.x += rc.x; x1.y += rc.y; x1.z += rd.x; x1.w += rd.y;
    float sum = x0.x+x0.y+x0.z+x0.w + x1.x+x1.y+x1.z+x1.w;
    float sq  = x0.x*x0.x+x0.y*x0.y+x0.z*x0.z+x0.w*x0.w
              + x1.x*x1.x+x1.y*x1.y+x1.z*x1.z+x1.w*x1.w;
    #pragma unroll
    for (int o = 16; o > 0; o >>= 1) {
        sum += __shfl_xor_sync(0xffffffffu, sum, o);
        sq  += __shfl_xor_sync(0xffffffffu, sq,  o);
    }
    float mu  = sum * (1.f/CC);
    float var = sq  * (1.f/CC) - mu*mu;
    float inv = rsqrtf(var + 1e-5f);
    float4 g0 = *(const float4*)(g  + lane*4);
    float4 g1 = *(const float4*)(g  + 128 + lane*4);
    float4 b0 = *(const float4*)(bb + lane*4);
    float4 b1 = *(const float4*)(bb + 128 + lane*4);
    float4 o0, o1;
    o0.x = (x0.x-mu)*inv*g0.x + b0.x; o0.y = (x0.y-mu)*inv*g0.y + b0.y;
    o0.z = (x0.z-mu)*inv*g0.z + b0.z; o0.w = (x0.w-mu)*inv*g0.w + b0.w;
    o1.x = (x1.x-mu)*inv*g1.x + b1.x; o1.y = (x1.y-mu)*inv*g1.y + b1.y;
    o1.z = (x1.z-mu)*inv*g1.z + b1.z; o1.w = (x1.w-mu)*inv*g1.w + b1.w;
    *(float4*)(out + base + lane*4)       = o0;
    *(float4*)(out + base + 128 + lane*4) = o1;
    if (out_h) {
        uint2 h0, h1;
        ((__half2*)&h0)[0] = __floats2half2_rn(o0.x, o0.y);
        ((__half2*)&h0)[1] = __floats2half2_rn(o0.z, o0.w);
        ((__half2*)&h1)[0] = __floats2half2_rn(o1.x, o1.y);
        ((__half2*)&h1)[1] = __floats2half2_rn(o1.z, o1.w);
        *(uint2*)(out_h + base + lane*4)       = h0;
        *(uint2*)(out_h + base + 128 + lane*4) = h1;
    }
    if (out_hp) {
        size_t pb = (tok & (NW*TT - 1)) * CC;
        float4 p0 = *(const float4*)(g_pos + pb + lane*4);
        float4 p1 = *(const float4*)(g_pos + pb + 128 + lane*4);
        uint2 h0, h1;
        ((__half2*)&h0)[0] = __floats2half2_rn(o0.x + p0.x, o0.y + p0.y);
        ((__half2*)&h0)[1] = __floats2half2_rn(o0.z + p0.z, o0.w + p0.w);
        ((__half2*)&h1)[0] = __floats2half2_rn(o1.x + p1.x, o1.y + p1.y);
        ((__half2*)&h1)[1] = __floats2half2_rn(o1.z + p1.z, o1.w + p1.w);
        *(uint2*)(out_hp + base + lane*4)       = h0;
        *(uint2*)(out_hp + base + 128 + lane*4) = h1;
    }
}

// ---------------- final scatter (tiled transpose): out = bm + x*valid ------------
__global__ void output_kernel(const float* __restrict__ bm, float* __restrict__ out)
{
    __shared__ float tile[32][33];
    int xt = blockIdx.x, y = blockIdx.y;
    int b = blockIdx.z >> 3, ct = blockIdx.z & 7;
    int c0 = ct * 32, x0 = xt * 32;
    int wy = y >> 4, ty = y & 15;
    int hi = threadIdx.x >> 5, lane = threadIdx.x & 31;
    #pragma unroll
    for (int p = 0; p < 4; p++) {
        int xj = hi + p*8;
        int x = x0 + xj;
        int w = wy*8 + (x >> 4);
        int t = ty*16 + (x & 15);
        float vv = g_valid[b*NW + w];
        tile[xj][lane] = vv == 0.f ? 0.f
            : g_x[((size_t)(b*NW + w)*TT + t)*CC + c0 + lane];
    }
    __syncthreads();
    #pragma unroll
    for (int p = 0; p < 4; p++) {
        int c = hi + p*8;
        size_t idx = ((size_t)(b*CC + c0 + c)*HH + y)*WW + x0 + lane;
        out[idx] = bm[idx] + tile[lane][c];
    }
}

__global__ void valid_out_kernel(float* __restrict__ out)
{
    int i = threadIdx.x;
    out[(size_t)BB*CC*HH*WW + i] = g_valid[i];
}

// =================================================================================
extern "C" void kernel_launch(void* const* d_in, const int* in_sizes, int n_in,
                              void* d_out, int out_size)
{
    float  *p_x, *p_src, *p_valid;
    __half *p_xh, *p_xph, *p_qkvh, *p_atth, *p_srch, *p_yh, *p_ffh, *p_w16;
    cudaGetSymbolAddress((void**)&p_x,    g_x);
    cudaGetSymbolAddress((void**)&p_src,  g_src);
    cudaGetSymbolAddress((void**)&p_valid, g_valid);
    cudaGetSymbolAddress((void**)&p_xh,   g_xh);
    cudaGetSymbolAddress((void**)&p_xph,  g_xph);
    cudaGetSymbolAddress((void**)&p_qkvh, g_qkvh);
    cudaGetSymbolAddress((void**)&p_atth, g_atth);
    cudaGetSymbolAddress((void**)&p_srch, g_srch);
    cudaGetSymbolAddress((void**)&p_yh,   g_yh);
    cudaGetSymbolAddress((void**)&p_ffh,  g_ffh);
    cudaGetSymbolAddress((void**)&p_w16,  g_w16);

    static int smem_set = 0;
    if (!smem_set) {
        cudaFuncSetAttribute(gemm_f16, cudaFuncAttributeMaxDynamicSharedMemorySize, 98304);
        smem_set = 1;
    }

    int sh = (n_in > 2 && in_sizes[2] == 1) ? 0 : -1;
    const float* bm    = (const float*)d_in[0];
    const float* defe  = (const float*)d_in[1];
    const float* gp    = (const float*)d_in[3+sh];
    const float* rw1   = (const float*)d_in[4+sh];
    const float* rb1   = (const float*)d_in[5+sh];
    const float* rw2   = (const float*)d_in[6+sh];
    const float* rb2   = (const float*)d_in[7+sh];
    const float* inw   = (const float*)d_in[8+sh];
    const float* inb   = (const float*)d_in[9+sh];
    const float* ow    = (const float*)d_in[10+sh];
    const float* ob    = (const float*)d_in[11+sh];
    const float* l1w   = (const float*)d_in[12+sh];
    const float* l1b   = (const float*)d_in[13+sh];
    const float* l2w   = (const float*)d_in[14+sh];
    const float* l2b   = (const float*)d_in[15+sh];
    const float* g1    = (const float*)d_in[16+sh];
    const float* b1    = (const float*)d_in[17+sh];
    const float* g2    = (const float*)d_in[18+sh];
    const float* b2    = (const float*)d_in[19+sh];

    // ---- prep ----
    convertw_kernel<<<(196608+255)/256, 256>>>(inw, p_w16 + W_INW, 196608);
    convertw_kernel<<<(65536 +255)/256, 256>>>(ow,  p_w16 + W_OW,  65536);
    convertw_kernel<<<(262144+255)/256, 256>>>(l1w, p_w16 + W_L1,  262144);
    convertw_kernel<<<(262144+255)/256, 256>>>(l2w, p_w16 + W_L2,  262144);
    rel_kernel<<<TT, 256>>>(rw1, rb1, rw2, rb2);
    pos_kernel<<<(NW*TT*CC + 255)/256, 256>>>(gp);
    valid_kernel<<<BB*NW, 256>>>(defe);
    partition_kernel<<<dim3(4, 128, 32), 256>>>(bm);   // writes x, x_h, xp_h (valid only)

    dim3 gQKV(6, NTOK/128);
    dim3 gFF1(8, NTOK/128);
    const int GSM = 98304;

    for (int stage = 0; stage < 2; stage++) {
        // fused QKV: Q,K blocks (m0<512) read xp_h; V blocks read x_h
        gemm_f16<<<gQKV, 128, GSM>>>(p_xph, p_xh, 512, p_w16 + W_INW, inb, p_qkvh, 768, CC, 0, p_valid);
        if (stage == 0)
            attn_within_kernel<<<dim3(BB*NW, NHEAD), 256>>>(p_qkvh, p_atth, p_valid);
        else
            attn_cross_kernel<<<dim3(BB*TT, NHEAD), 64>>>(p_qkvh, p_valid, p_atth);
        gemm_f16<<<dim3(2, NTOK/128), 128, GSM>>>(p_atth, p_atth, 0, p_w16 + W_OW, ob, p_yh, CC, CC, 0, p_valid);
        // src = LN(x + y); also emit fp16 src for FFN1
        ln_kernel<<<NTOK/8, 256>>>(p_x, p_yh, g1, b1, p_src, p_srch, (__half*)0, p_valid);
        gemm_f16<<<gFF1, 128, GSM>>>(p_srch, p_srch, 0, p_w16 + W_L1, l1b, p_ffh, DFF, CC, 1, p_valid);
        gemm_f16<<<dim3(2, NTOK/128), 128, GSM>>>(p_ffh, p_ffh, 0, p_w16 + W_L2, l2b, p_yh, CC, DFF, 0, p_valid);
        // x = LN(src + ff); stage0 also emits x_h and xp_h for stage1 QKV
        ln_kernel<<<NTOK/8, 256>>>(p_src, p_yh, g2, b2, p_x,
                                   stage == 0 ? p_xh  : (__half*)0,
                                   stage == 0 ? p_xph : (__half*)0, p_valid);
    }

    // ---- output ----
    output_kernel<<<dim3(4, 128, 32), 256>>>(bm, (float*)d_out);
    if (out_size >= BB*CC*HH*WW + BB*NW)
        valid_out_kernel<<<1, BB*NW>>>((float*)d_out);
}

// round 15
// speedup vs baseline: 2.9914x; 1.3481x over previous
#include <cuda_runtime.h>
#include <cuda_fp16.h>
#include <math.h>
#include <stdint.h>

// Problem constants
#define BB 4
#define CC 256
#define HH 128
#define WW 128
#define WS 16
#define NWH 8
#define NWW 8
#define NW 64
#define TT 256
#define NTOK (BB*NW*TT)  // 65536
#define NHEAD 8
#define DH 32
#define DFF 1024

// weight offsets in g_w16
#define W_INW 0
#define W_OW  196608
#define W_L1  262144
#define W_L2  524288
#define W_TOT 786432

// ---------------- device scratch (allocation-free: __device__ globals) ----------
// Never pass these names directly as kernel args from host (host shadow + GB300
// ATS silently reads host memory). Resolved via cudaGetSymbolAddress.
// fp16 buffers of INVALID windows are never written (zero/stale); all consumers mask.
__device__ float  g_x  [NTOK*CC];     // fp32 residual spine
__device__ float  g_src[NTOK*CC];
__device__ float  g_pos[NW*TT*CC];
__device__ float  g_rel[TT*CC];
__device__ float  g_valid[BB*NW];
__device__ __half g_xh  [NTOK*CC];
__device__ __half g_xph [NTOK*CC];
__device__ __half g_qkvh[NTOK*768];
__device__ __half g_atth[NTOK*CC];
__device__ __half g_srch[NTOK*CC];
__device__ __half g_yh  [NTOK*CC];
__device__ __half g_ffh [NTOK*DFF];
__device__ __half g_w16 [W_TOT];

// ---------------- fp16 helpers ----------------------------------------------------
__device__ __forceinline__ void h8_to_f8(uint4 u, float4* dst) {
    __half2* h = (__half2*)&u;
    float2 f0 = __half22float2(h[0]), f1 = __half22float2(h[1]);
    float2 f2 = __half22float2(h[2]), f3 = __half22float2(h[3]);
    dst[0] = make_float4(f0.x, f0.y, f1.x, f1.y);
    dst[1] = make_float4(f2.x, f2.y, f3.x, f3.y);
}
__device__ __forceinline__ uint4 f8_to_h8(float4 a, float4 b) {
    uint4 u;
    ((__half2*)&u)[0] = __floats2half2_rn(a.x, a.y);
    ((__half2*)&u)[1] = __floats2half2_rn(a.z, a.w);
    ((__half2*)&u)[2] = __floats2half2_rn(b.x, b.y);
    ((__half2*)&u)[3] = __floats2half2_rn(b.z, b.w);
    return u;
}
__device__ __forceinline__ uint32_t pack_h2(float a, float b) {
    __half2 h = __floats2half2_rn(a, b);
    return *(uint32_t*)&h;
}

// ---------------- all-weights conversion fp32 -> fp16 (one launch) ----------------
__global__ void convertw_all(const float* __restrict__ inw, const float* __restrict__ ow,
                             const float* __restrict__ l1w, const float* __restrict__ l2w,
                             __half* __restrict__ o)
{
    int i = blockIdx.x * 256 + threadIdx.x;   // grid = W_TOT/256
    float v;
    if      (i < W_OW) v = inw[i];
    else if (i < W_L1) v = ow [i - W_OW];
    else if (i < W_L2) v = l1w[i - W_L1];
    else               v = l2w[i - W_L2];
    o[i] = __float2half_rn(v);
}

// ---------------- rel position MLP (256 blocks — NOT fused into pos!) -------------
__global__ void rel_kernel(const float* __restrict__ w1, const float* __restrict__ b1,
                           const float* __restrict__ w2, const float* __restrict__ b2)
{
    __shared__ float hid[64];
    int t = blockIdx.x;
    float cy = (float)(t / WS) / (float)(WS - 1);
    float cx = (float)(t % WS) / (float)(WS - 1);
    if (threadIdx.x < 64) {
        float h = cy * w1[threadIdx.x*2+0] + cx * w1[threadIdx.x*2+1] + b1[threadIdx.x];
        hid[threadIdx.x] = fmaxf(h, 0.f);
    }
    __syncthreads();
    int c = threadIdx.x;
    float s = b2[c];
    #pragma unroll 8
    for (int j = 0; j < 64; j++) s += hid[j] * w2[c*64 + j];
    g_rel[t*CC + c] = s;
}

// ---------------- pos[w,t,c] = glob_pos windowed + rel[t,c] ---------------------
__global__ void pos_kernel(const float* __restrict__ gp)
{
    int idx = blockIdx.x * blockDim.x + threadIdx.x;
    if (idx >= NW*TT*CC) return;
    int c = idx % CC;
    int t = (idx / CC) % TT;
    int w = idx / (CC*TT);
    int wy = w / NWW, wx = w % NWW, ty = t / WS, tx = t % WS;
    g_pos[idx] = gp[(c*HH + wy*WS + ty)*WW + wx*WS + tx] + g_rel[t*CC + c];
}

// ---------------- valid[b,w] = maxpool(defe window) > 0 -------------------------
__global__ void valid_kernel(const float* __restrict__ defe)
{
    int bw = blockIdx.x;
    int b = bw / NW, w = bw % NW;
    int t = threadIdx.x;
    int wy = w / NWW, wx = w % NWW, ty = t / WS, tx = t % WS;
    float v = defe[(b*HH + wy*WS + ty)*WW + wx*WS + tx];
    __shared__ float red[256];
    red[t] = v; __syncthreads();
    for (int s = 128; s > 0; s >>= 1) {
        if (t < s) red[t] = fmaxf(red[t], red[t+s]);
        __syncthreads();
    }
    if (t == 0) g_valid[bw] = red[0] > 0.f ? 1.f : 0.f;
}

// ---------------- window partition (tiled transpose), valid windows only ----------
__global__ void partition_kernel(const float* __restrict__ bm)
{
    __shared__ float tile[32][33];
    int xt = blockIdx.x, y = blockIdx.y;
    int b = blockIdx.z >> 3, ct = blockIdx.z & 7;
    int c0 = ct * 32, x0 = xt * 32;
    int wy = y >> 4;
    int wA = wy*8 + (x0 >> 4), wB = wy*8 + ((x0+16) >> 4);
    if (g_valid[b*NW + wA] == 0.f && g_valid[b*NW + wB] == 0.f) return;
    int ci = threadIdx.x >> 5, xi = threadIdx.x & 31;
    #pragma unroll
    for (int p = 0; p < 4; p++) {
        int c = ci + p*8;
        tile[c][xi] = bm[((size_t)(b*CC + c0 + c)*HH + y)*WW + x0 + xi];
    }
    __syncthreads();
    int ty = y & 15;
    #pragma unroll
    for (int p = 0; p < 4; p++) {
        int xj = ci + p*8;
        int x = x0 + xj;
        int w = wy*8 + (x >> 4);
        if (g_valid[b*NW + w] == 0.f) continue;
        int t = ty*16 + (x & 15);
        float v = tile[xi][xj];
        size_t tok = (size_t)(b*NW + w)*TT + t;
        size_t idx = tok*CC + c0 + xi;
        g_x  [idx] = v;
        g_xh [idx] = __float2half_rn(v);
        g_xph[idx] = __float2half_rn(v + g_pos[((size_t)w*TT + t)*CC + c0 + xi]);
    }
}

// ================= FP16 tensor-core GEMM (3-stage cp.async, BK=64) ===============
// Block 128x128, 4 warps (2m x 2n), warp tile 64x64. 2 CTAs/SM. Early-exit invalid.

__device__ __forceinline__ void mma_f16(float c[4], const uint32_t a[4], const uint32_t b[2]) {
    asm volatile(
        "mma.sync.aligned.m16n8k16.row.col.f32.f16.f16.f32 "
        "{%0,%1,%2,%3}, {%4,%5,%6,%7}, {%8,%9}, {%0,%1,%2,%3};"
        : "+f"(c[0]), "+f"(c[1]), "+f"(c[2]), "+f"(c[3])
        : "r"(a[0]), "r"(a[1]), "r"(a[2]), "r"(a[3]), "r"(b[0]), "r"(b[1]));
}

__device__ __forceinline__ void cp_async16(uint32_t dst, const void* src) {
    asm volatile("cp.async.cg.shared.global [%0], [%1], 16;" :: "r"(dst), "l"(src));
}

__global__ __launch_bounds__(128)
void gemm_f16(const __half* __restrict__ A0, const __half* __restrict__ A1, int mswitch,
              const __half* __restrict__ Wt, const float* __restrict__ bias,
              __half* __restrict__ C, int ldC, int K, int relu,
              const float* __restrict__ vld)
{
    int n0 = blockIdx.y << 7;
    if (vld[n0 >> 8] == 0.f) return;
    extern __shared__ char smc[];
    uint32_t asB = (uint32_t)__cvta_generic_to_shared(smc);
    uint32_t bsB = asB + 3*16384;
    int tid = threadIdx.x;
    int m0 = blockIdx.x << 7;
    const __half* A = (m0 < mswitch) ? A0 : A1;
    int warp = tid >> 5, lane = tid & 31;
    int wm = (warp & 1) << 6;
    int wn = (warp >> 1) << 6;
    int g = lane >> 2, q = lane & 3;

    int srow = tid >> 3;
    int scb  = tid & 7;

    float c[4][8][4] = {};
    int nk = K >> 6;

#define LOAD_STAGE(st, k0)                                                           \
    {                                                                                \
        _Pragma("unroll")                                                            \
        for (int p = 0; p < 8; p++) {                                                \
            int row = (p << 4) + srow;                                               \
            uint32_t sof = (st)*16384u + (row << 7) + ((scb ^ (row & 7)) << 4);      \
            cp_async16(asB + sof, A  + (size_t)(n0 + row) * K + (k0) + (scb << 3));  \
            cp_async16(bsB + sof, Wt + (size_t)(m0 + row) * K + (k0) + (scb << 3));  \
        }                                                                            \
        asm volatile("cp.async.commit_group;");                                      \
    }

    LOAD_STAGE(0, 0)
    if (nk > 1) LOAD_STAGE(1, 64)
    for (int kt = 0; kt < nk; kt++) {
        if (kt + 1 < nk) asm volatile("cp.async.wait_group 1;");
        else             asm volatile("cp.async.wait_group 0;");
        __syncthreads();
        if (kt + 2 < nk) {
            int st = (kt + 2) % 3;
            LOAD_STAGE(st, (kt + 2) << 6)
        }
        int cur = kt % 3;
        const uint32_t* Ac = (const uint32_t*)(smc + cur*16384);
        const uint32_t* Bc = (const uint32_t*)(smc + 3*16384 + cur*16384);
        #pragma unroll
        for (int kk = 0; kk < 4; kk++) {
            int ch0 = kk << 1, ch1 = ch0 + 1;
            uint32_t af[4][4];
            #pragma unroll
            for (int i = 0; i < 4; i++) {
                int r0 = wm + (i << 4) + g, r1 = r0 + 8;
                af[i][0] = Ac[(r0 << 5) + ((ch0 ^ (r0 & 7)) << 2) + q];
                af[i][1] = Ac[(r1 << 5) + ((ch0 ^ (r1 & 7)) << 2) + q];
                af[i][2] = Ac[(r0 << 5) + ((ch1 ^ (r0 & 7)) << 2) + q];
                af[i][3] = Ac[(r1 << 5) + ((ch1 ^ (r1 & 7)) << 2) + q];
            }
            uint32_t bf[8][2];
            #pragma unroll
            for (int j = 0; j < 8; j++) {
                int n = wn + (j << 3) + g;
                bf[j][0] = Bc[(n << 5) + ((ch0 ^ (n & 7)) << 2) + q];
                bf[j][1] = Bc[(n << 5) + ((ch1 ^ (n & 7)) << 2) + q];
            }
            #pragma unroll
            for (int i = 0; i < 4; i++)
                #pragma unroll
                for (int j = 0; j < 8; j++)
                    mma_f16(c[i][j], af[i], bf[j]);
        }
        __syncthreads();
    }
#undef LOAD_STAGE

    #pragma unroll
    for (int i = 0; i < 4; i++) {
        int row = n0 + wm + (i << 4) + g;
        #pragma unroll
        for (int j = 0; j < 8; j++) {
            int col = m0 + wn + (j << 3) + (q << 1);
            float b0 = bias[col], b1 = bias[col+1];
            float v0 = c[i][j][0] + b0, v1 = c[i][j][1] + b1;
            float v2 = c[i][j][2] + b0, v3 = c[i][j][3] + b1;
            if (relu) {
                v0 = fmaxf(v0, 0.f); v1 = fmaxf(v1, 0.f);
                v2 = fmaxf(v2, 0.f); v3 = fmaxf(v3, 0.f);
            }
            *(__half2*)&C[(size_t) row      * ldC + col] = __floats2half2_rn(v0, v1);
            *(__half2*)&C[(size_t)(row + 8) * ldC + col] = __floats2half2_rn(v2, v3);
        }
    }
}

// ================= within-window attention: flash-style MMA =======================
// Block = (window, head), 256 threads = 8 warps x 32 queries. 4 key tiles of 64.
// No-max softmax: O = sum_tiles P@V, s = sum rowsum(P), final O/s.
// P fragments repacked fp32->fp16 in registers (C m16n8 layout == half A m16k16).
#define QSC (0.17677669529663687f * 1.4426950408889634f)

__global__ __launch_bounds__(256)
void attn_within_kernel(const __half* __restrict__ qkv, __half* __restrict__ gatt,
                        const float* __restrict__ vld)
{
    int bw = blockIdx.x;
    if (vld[bw] == 0.f) return;
    __shared__ char sm[16384];   // Ks[2] @0 (64x32h, 64B rows, 4KB ea); Vt[2] @8192 (32x64h, 128B rows)
    uint32_t sb = (uint32_t)__cvta_generic_to_shared(sm);
    int h = blockIdx.y;
    int tid = threadIdx.x;
    int warp = tid >> 5, lane = tid & 31;
    int g = lane >> 2, q = lane & 3;
    int wq0 = warp << 5;
    size_t base = (size_t)bw * TT;

    // Q fragments in registers (k = dh = 32 -> 2 k16 chunks), loaded once
    uint32_t aq[2][2][4];
    #pragma unroll
    for (int i = 0; i < 2; i++) {
        const __half* q0 = qkv + (base + wq0 + (i << 4) + g) * 768 + h * DH;
        const __half* q1 = q0 + 8 * 768;
        #pragma unroll
        for (int kk = 0; kk < 2; kk++) {
            aq[i][kk][0] = *(const uint32_t*)(q0 + (kk << 4) + (q << 1));
            aq[i][kk][1] = *(const uint32_t*)(q1 + (kk << 4) + (q << 1));
            aq[i][kk][2] = *(const uint32_t*)(q0 + (kk << 4) + 8 + (q << 1));
            aq[i][kk][3] = *(const uint32_t*)(q1 + (kk << 4) + 8 + (q << 1));
        }
    }

    float o[2][4][4] = {};
    float s[2][2] = {};

    int skey = tid >> 2, sch = tid & 3;   // staging: 64 keys x 4 chunks of 16B

#define ATT_STAGE(b, kt)                                                              \
    {                                                                                 \
        const __half* kv = qkv + (base + ((kt) << 6) + skey) * 768 + h * DH;          \
        cp_async16(sb + (b)*4096u + (skey << 6) + ((sch ^ (skey & 3)) << 4),          \
                   kv + 256 + (sch << 3));                                            \
        asm volatile("cp.async.commit_group;");                                       \
        uint4 vv = *(const uint4*)(kv + 512 + (sch << 3));                            \
        const __half* vh = (const __half*)&vv;                                        \
        _Pragma("unroll")                                                             \
        for (int e = 0; e < 8; e++) {                                                 \
            int dh = (sch << 3) + e;                                                  \
            *(__half*)(sm + 8192 + (b)*4096 + (dh << 7)                               \
                       + (((skey >> 3) ^ (dh & 7)) << 4) + ((skey & 7) << 1)) = vh[e];\
        }                                                                             \
    }

    ATT_STAGE(0, 0)
    for (int kt = 0; kt < 4; kt++) {
        int buf = kt & 1;
        if (kt < 3) {
            ATT_STAGE(buf ^ 1, kt + 1)
            asm volatile("cp.async.wait_group 1;");
        } else {
            asm volatile("cp.async.wait_group 0;");
        }
        __syncthreads();

        // ---- S = Q @ K^T  (64 keys) ----
        float c[2][8][4] = {};
        const char* ks = sm + buf*4096;
        #pragma unroll
        for (int kk = 0; kk < 2; kk++) {
            int ch0 = kk << 1, ch1 = ch0 + 1;
            uint32_t bf[8][2];
            #pragma unroll
            for (int j = 0; j < 8; j++) {
                int n = (j << 3) + g;
                bf[j][0] = *(const uint32_t*)(ks + (n << 6) + ((ch0 ^ (n & 3)) << 4) + (q << 2));
                bf[j][1] = *(const uint32_t*)(ks + (n << 6) + ((ch1 ^ (n & 3)) << 4) + (q << 2));
            }
            #pragma unroll
            for (int i = 0; i < 2; i++)
                #pragma unroll
                for (int j = 0; j < 8; j++)
                    mma_f16(c[i][j], aq[i][kk], bf[j]);
        }

        // ---- P = exp2(S*QSC), row sums ----
        #pragma unroll
        for (int i = 0; i < 2; i++)
            #pragma unroll
            for (int j = 0; j < 8; j++) {
                float p0 = exp2f(c[i][j][0] * QSC);
                float p1 = exp2f(c[i][j][1] * QSC);
                float p2 = exp2f(c[i][j][2] * QSC);
                float p3 = exp2f(c[i][j][3] * QSC);
                c[i][j][0] = p0; c[i][j][1] = p1; c[i][j][2] = p2; c[i][j][3] = p3;
                s[i][0] += p0 + p1;
                s[i][1] += p2 + p3;
            }

        // ---- O += P @ V  (P fp16 A-fragments from C-fragments, V from Vt smem) ----
        const char* vt = sm + 8192 + buf*4096;
        #pragma unroll
        for (int kk = 0; kk < 4; kk++) {          // key chunks of 16
            int ch0 = kk << 1, ch1 = ch0 + 1;
            uint32_t bv[4][2];
            #pragma unroll
            for (int j2 = 0; j2 < 4; j2++) {
                int n = (j2 << 3) + g;            // dh row (0..31)
                bv[j2][0] = *(const uint32_t*)(vt + (n << 7) + ((ch0 ^ (n & 7)) << 4) + (q << 2));
                bv[j2][1] = *(const uint32_t*)(vt + (n << 7) + ((ch1 ^ (n & 7)) << 4) + (q << 2));
            }
            #pragma unroll
            for (int i = 0; i < 2; i++) {
                uint32_t a[4];
                a[0] = pack_h2(c[i][2*kk  ][0], c[i][2*kk  ][1]);
                a[1] = pack_h2(c[i][2*kk  ][2], c[i][2*kk  ][3]);
                a[2] = pack_h2(c[i][2*kk+1][0], c[i][2*kk+1][1]);
                a[3] = pack_h2(c[i][2*kk+1][2], c[i][2*kk+1][3]);
                #pragma unroll
                for (int j2 = 0; j2 < 4; j2++)
                    mma_f16(o[i][j2], a, bv[j2]);
            }
        }
        __syncthreads();
    }
#undef ATT_STAGE

    // ---- finalize: reduce s across quad lanes, normalize, store ----
    #pragma unroll
    for (int i = 0; i < 2; i++) {
        #pragma unroll
        for (int hf = 0; hf < 2; hf++) {
            s[i][hf] += __shfl_xor_sync(0xffffffffu, s[i][hf], 1);
            s[i][hf] += __shfl_xor_sync(0xffffffffu, s[i][hf], 2);
        }
        float inv0 = s[i][0] > 0.f ? 1.f / s[i][0] : 0.f;
        float inv1 = s[i][1] > 0.f ? 1.f / s[i][1] : 0.f;
        size_t row = base + wq0 + (i << 4) + g;
        #pragma unroll
        for (int j2 = 0; j2 < 4; j2++) {
            int col = h * DH + (j2 << 3) + (q << 1);
            *(__half2*)(gatt + row*CC + col) =
                __floats2half2_rn(o[i][j2][0] * inv0, o[i][j2][1] * inv0);
            *(__half2*)(gatt + (row + 8)*CC + col) =
                __floats2half2_rn(o[i][j2][2] * inv1, o[i][j2][3] * inv1);
        }
    }
}

// ---------------- cross-window attention (key padding mask) ----------------------
__global__ void attn_cross_kernel(const __half* __restrict__ qkv,
                                  const float* __restrict__ gvalid,
                                  __half* __restrict__ gatt)
{
    __shared__ float4 ks[NW*8];
    __shared__ float4 vs[NW*8];
    __shared__ float mk[NW];
    int bt = blockIdx.x;
    int b = bt / TT, t = bt % TT;
    int h = blockIdx.y;
    int wq = threadIdx.x;
    if (threadIdx.x < NW) mk[threadIdx.x] = gvalid[b*NW + threadIdx.x];
    __syncthreads();
    for (int i = threadIdx.x; i < NW*4; i += 64) {
        int w = i >> 2, d = i & 3;
        if (mk[w] == 0.f) continue;
        const __half* rb = qkv + ((size_t)(b*NW + w)*TT + t)*768 + h*DH;
        h8_to_f8(*(const uint4*)(rb + 256 + d*8), &ks[w*8 + d*2]);
        h8_to_f8(*(const uint4*)(rb + 512 + d*8), &vs[w*8 + d*2]);
    }
    __syncthreads();
    if (mk[wq] == 0.f) return;
    float4 qr[8];
    size_t qtok = (size_t)(b*NW + wq)*TT + t;
    const __half* qp = qkv + qtok*768 + h*DH;
    #pragma unroll
    for (int j = 0; j < 4; j++) h8_to_f8(*(const uint4*)(qp + j*8), &qr[j*2]);
    #pragma unroll
    for (int j = 0; j < 8; j++) {
        qr[j].x *= QSC; qr[j].y *= QSC; qr[j].z *= QSC; qr[j].w *= QSC;
    }
    float s = 0.f;
    float4 acc[8] = {};
    for (int i = 0; i < NW; i++) {
        if (mk[i] == 0.f) continue;
        const float4* kp = &ks[i*8];
        float sc = 0.f;
        #pragma unroll
        for (int j = 0; j < 8; j++) {
            float4 k4 = kp[j];
            sc = fmaf(qr[j].x, k4.x, sc); sc = fmaf(qr[j].y, k4.y, sc);
            sc = fmaf(qr[j].z, k4.z, sc); sc = fmaf(qr[j].w, k4.w, sc);
        }
        float e = exp2f(sc);
        s += e;
        const float4* vp = &vs[i*8];
        #pragma unroll
        for (int j = 0; j < 8; j++) {
            float4 v4 = vp[j];
            acc[j].x = fmaf(e, v4.x, acc[j].x); acc[j].y = fmaf(e, v4.y, acc[j].y);
            acc[j].z = fmaf(e, v4.z, acc[j].z); acc[j].w = fmaf(e, v4.w, acc[j].w);
        }
    }
    float inv = s > 0.f ? 1.f / s : 0.f;
    __half* op = gatt + qtok*CC + h*DH;
    #pragma unroll
    for (int j = 0; j < 4; j++) {
        float4 a = acc[2*j], b4 = acc[2*j+1];
        a.x *= inv; a.y *= inv; a.z *= inv; a.w *= inv;
        b4.x *= inv; b4.y *= inv; b4.z *= inv; b4.w *= inv;
        *(uint4*)(op + j*8) = f8_to_h8(a, b4);
    }
}

// ---------------- fused residual + LayerNorm (warp per token) --------------------
__global__ void ln_kernel(const float* __restrict__ a, const __half* __restrict__ r,
                          const float* __restrict__ g, const float* __restrict__ bb,
                          float* __restrict__ out, __half* __restrict__ out_h,
                          __half* __restrict__ out_hp, const float* __restrict__ vld)
{
    if (vld[blockIdx.x >> 5] == 0.f) return;
    int warp = threadIdx.x >> 5, lane = threadIdx.x & 31;
    size_t tok = (size_t)blockIdx.x * 8 + warp;
    size_t base = tok * CC;
    float4 x0 = *(const float4*)(a + base + lane*4);
    float4 x1 = *(const float4*)(a + base + 128 + lane*4);
    uint2 ru0 = *(const uint2*)(r + base + lane*4);
    uint2 ru1 = *(const uint2*)(r + base + 128 + lane*4);
    float2 ra = __half22float2(*(__half2*)&ru0.x), rb2 = __half22float2(*(__half2*)&ru0.y);
    float2 rc = __half22float2(*(__half2*)&ru1.x), rd = __half22float2(*(__half2*)&ru1.y);
    x0.x += ra.x; x0.y += ra.y; x0.z += rb2.x; x0.w += rb2.y;
    x1.x += rc.x; x1.y += rc.y; x1.z += rd.x; x1.w += rd.y;
    float sum = x0.x+x0.y+x0.z+x0.w + x1.x+x1.y+x1.z+x1.w;
    float sq  = x0.x*x0.x+x0.y*x0.y+x0.z*x0.z+x0.w*x0.w
              + x1.x*x1.x+x1.y*x1.y+x1.z*x1.z+x1.w*x1.w;
    #pragma unroll
    for (int o = 16; o > 0; o >>= 1) {
        sum += __shfl_xor_sync(0xffffffffu, sum, o);
        sq  += __shfl_xor_sync(0xffffffffu, sq,  o);
    }
    float mu  = sum * (1.f/CC);
    float var = sq  * (1.f/CC) - mu*mu;
    float inv = rsqrtf(var + 1e-5f);
    float4 g0 = *(const float4*)(g  + lane*4);
    float4 g1 = *(const float4*)(g  + 128 + lane*4);
    float4 b0 = *(const float4*)(bb + lane*4);
    float4 b1 = *(const float4*)(bb + 128 + lane*4);
    float4 o0, o1;
    o0.x = (x0.x-mu)*inv*g0.x + b0.x; o0.y = (x0.y-mu)*inv*g0.y + b0.y;
    o0.z = (x0.z-mu)*inv*g0.z + b0.z; o0.w = (x0.w-mu)*inv*g0.w + b0.w;
    o1.x = (x1.x-mu)*inv*g1.x + b1.x; o1.y = (x1.y-mu)*inv*g1.y + b1.y;
    o1.z = (x1.z-mu)*inv*g1.z + b1.z; o1.w = (x1.w-mu)*inv*g1.w + b1.w;
    *(float4*)(out + base + lane*4)       = o0;
    *(float4*)(out + base + 128 + lane*4) = o1;
    if (out_h) {
        uint2 h0, h1;
        ((__half2*)&h0)[0] = __floats2half2_rn(o0.x, o0.y);
        ((__half2*)&h0)[1] = __floats2half2_rn(o0.z, o0.w);
        ((__half2*)&h1)[0] = __floats2half2_rn(o1.x, o1.y);
        ((__half2*)&h1)[1] = __floats2half2_rn(o1.z, o1.w);
        *(uint2*)(out_h + base + lane*4)       = h0;
        *(uint2*)(out_h + base + 128 + lane*4) = h1;
    }
    if (out_hp) {
        size_t pb = (tok & (NW*TT - 1)) * CC;
        float4 p0 = *(const float4*)(g_pos + pb + lane*4);
        float4 p1 = *(const float4*)(g_pos + pb + 128 + lane*4);
        uint2 h0, h1;
        ((__half2*)&h0)[0] = __floats2half2_rn(o0.x + p0.x, o0.y + p0.y);
        ((__half2*)&h0)[1] = __floats2half2_rn(o0.z + p0.z, o0.w + p0.w);
        ((__half2*)&h1)[0] = __floats2half2_rn(o1.x + p1.x, o1.y + p1.y);
        ((__half2*)&h1)[1] = __floats2half2_rn(o1.z + p1.z, o1.w + p1.w);
        *(uint2*)(out_hp + base + lane*4)       = h0;
        *(uint2*)(out_hp + base + 128 + lane*4) = h1;
    }
}

// ---------------- final scatter (tiled transpose): out = bm + x*valid ------------
__global__ void output_kernel(const float* __restrict__ bm, float* __restrict__ out)
{
    __shared__ float tile[32][33];
    int xt = blockIdx.x, y = blockIdx.y;
    int b = blockIdx.z >> 3, ct = blockIdx.z & 7;
    int c0 = ct * 32, x0 = xt * 32;
    int wy = y >> 4, ty = y & 15;
    int hi = threadIdx.x >> 5, lane = threadIdx.x & 31;
    #pragma unroll
    for (int p = 0; p < 4; p++) {
        int xj = hi + p*8;
        int x = x0 + xj;
        int w = wy*8 + (x >> 4);
        int t = ty*16 + (x & 15);
        float vv = g_valid[b*NW + w];
        tile[xj][lane] = vv == 0.f ? 0.f
            : g_x[((size_t)(b*NW + w)*TT + t)*CC + c0 + lane];
    }
    __syncthreads();
    #pragma unroll
    for (int p = 0; p < 4; p++) {
        int c = hi + p*8;
        size_t idx = ((size_t)(b*CC + c0 + c)*HH + y)*WW + x0 + lane;
        out[idx] = bm[idx] + tile[lane][c];
    }
}

__global__ void valid_out_kernel(float* __restrict__ out)
{
    int i = threadIdx.x;
    out[(size_t)BB*CC*HH*WW + i] = g_valid[i];
}

// =================================================================================
extern "C" void kernel_launch(void* const* d_in, const int* in_sizes, int n_in,
                              void* d_out, int out_size)
{
    float  *p_x, *p_src, *p_valid;
    __half *p_xh, *p_xph, *p_qkvh, *p_atth, *p_srch, *p_yh, *p_ffh, *p_w16;
    cudaGetSymbolAddress((void**)&p_x,    g_x);
    cudaGetSymbolAddress((void**)&p_src,  g_src);
    cudaGetSymbolAddress((void**)&p_valid, g_valid);
    cudaGetSymbolAddress((void**)&p_xh,   g_xh);
    cudaGetSymbolAddress((void**)&p_xph,  g_xph);
    cudaGetSymbolAddress((void**)&p_qkvh, g_qkvh);
    cudaGetSymbolAddress((void**)&p_atth, g_atth);
    cudaGetSymbolAddress((void**)&p_srch, g_srch);
    cudaGetSymbolAddress((void**)&p_yh,   g_yh);
    cudaGetSymbolAddress((void**)&p_ffh,  g_ffh);
    cudaGetSymbolAddress((void**)&p_w16,  g_w16);

    static int smem_set = 0;
    if (!smem_set) {
        cudaFuncSetAttribute(gemm_f16, cudaFuncAttributeMaxDynamicSharedMemorySize, 98304);
        smem_set = 1;
    }

    int sh = (n_in > 2 && in_sizes[2] == 1) ? 0 : -1;
    const float* bm    = (const float*)d_in[0];
    const float* defe  = (const float*)d_in[1];
    const float* gp    = (const float*)d_in[3+sh];
    const float* rw1   = (const float*)d_in[4+sh];
    const float* rb1   = (const float*)d_in[5+sh];
    const float* rw2   = (const float*)d_in[6+sh];
    const float* rb2   = (const float*)d_in[7+sh];
    const float* inw   = (const float*)d_in[8+sh];
    const float* inb   = (const float*)d_in[9+sh];
    const float* ow    = (const float*)d_in[10+sh];
    const float* ob    = (const float*)d_in[11+sh];
    const float* l1w   = (const float*)d_in[12+sh];
    const float* l1b   = (const float*)d_in[13+sh];
    const float* l2w   = (const float*)d_in[14+sh];
    const float* l2b   = (const float*)d_in[15+sh];
    const float* g1    = (const float*)d_in[16+sh];
    const float* b1    = (const float*)d_in[17+sh];
    const float* g2    = (const float*)d_in[18+sh];
    const float* b2    = (const float*)d_in[19+sh];

    // ---- prep ----
    convertw_all<<<W_TOT/256, 256>>>(inw, ow, l1w, l2w, p_w16);
    rel_kernel<<<TT, 256>>>(rw1, rb1, rw2, rb2);
    pos_kernel<<<(NW*TT*CC + 255)/256, 256>>>(gp);
    valid_kernel<<<BB*NW, 256>>>(defe);
    partition_kernel<<<dim3(4, 128, 32), 256>>>(bm);

    dim3 gQKV(6, NTOK/128);
    dim3 gOP (2, NTOK/128);
    dim3 gFF1(8, NTOK/128);
    const int GSM = 98304;

    for (int stage = 0; stage < 2; stage++) {
        gemm_f16<<<gQKV, 128, GSM>>>(p_xph, p_xh, 512, p_w16 + W_INW, inb, p_qkvh, 768, CC, 0, p_valid);
        if (stage == 0)
            attn_within_kernel<<<dim3(BB*NW, NHEAD), 256>>>(p_qkvh, p_atth, p_valid);
        else
            attn_cross_kernel<<<dim3(BB*TT, NHEAD), 64>>>(p_qkvh, p_valid, p_atth);
        gemm_f16<<<gOP, 128, GSM>>>(p_atth, p_atth, 0, p_w16 + W_OW, ob, p_yh, CC, CC, 0, p_valid);
        ln_kernel<<<NTOK/8, 256>>>(p_x, p_yh, g1, b1, p_src, p_srch, (__half*)0, p_valid);
        gemm_f16<<<gFF1, 128, GSM>>>(p_srch, p_srch, 0, p_w16 + W_L1, l1b, p_ffh, DFF, CC, 1, p_valid);
        gemm_f16<<<gOP, 128, GSM>>>(p_ffh, p_ffh, 0, p_w16 + W_L2, l2b, p_yh, CC, DFF, 0, p_valid);
        ln_kernel<<<NTOK/8, 256>>>(p_src, p_yh, g2, b2, p_x,
                                   stage == 0 ? p_xh  : (__half*)0,
                                   stage == 0 ? p_xph : (__half*)0, p_valid);
    }

    // ---- output ----
    output_kernel<<<dim3(4, 128, 32), 256>>>(bm, (float*)d_out);
    if (out_size >= BB*CC*HH*WW + BB*NW)
        valid_out_kernel<<<1, BB*NW>>>((float*)d_out);
}

// round 16
// speedup vs baseline: 3.0583x; 1.0224x over previous
#include <cuda_runtime.h>
#include <cuda_fp16.h>
#include <math.h>
#include <stdint.h>

// Problem constants
#define BB 4
#define CC 256
#define HH 128
#define WW 128
#define WS 16
#define NWH 8
#define NWW 8
#define NW 64
#define TT 256
#define NTOK (BB*NW*TT)  // 65536
#define NHEAD 8
#define DH 32
#define DFF 1024

// weight offsets in g_w16
#define W_INW 0
#define W_OW  196608
#define W_L1  262144
#define W_L2  524288
#define W_TOT 786432

// PDL: every kernel synchronizes on its producer before any global read.
#if defined(__CUDA_ARCH__) && (__CUDA_ARCH__ >= 900)
#define GRID_DEP_SYNC() cudaGridDependencySynchronize()
#else
#define GRID_DEP_SYNC()
#endif

// ---------------- device scratch (allocation-free: __device__ globals) ----------
// Never pass these names directly as kernel args from host (host shadow + GB300
// ATS silently reads host memory). Resolved via cudaGetSymbolAddress.
// fp16 buffers of INVALID windows are never written (zero/stale); all consumers mask.
__device__ float  g_x  [NTOK*CC];     // fp32 residual spine
__device__ float  g_src[NTOK*CC];
__device__ float  g_pos[NW*TT*CC];
__device__ float  g_rel[TT*CC];
__device__ float  g_valid[BB*NW];
__device__ __half g_xh  [NTOK*CC];
__device__ __half g_xph [NTOK*CC];
__device__ __half g_qkvh[NTOK*768];
__device__ __half g_atth[NTOK*CC];
__device__ __half g_srch[NTOK*CC];
__device__ __half g_yh  [NTOK*CC];
__device__ __half g_ffh [NTOK*DFF];
__device__ __half g_w16 [W_TOT];

// ---------------- fp16 helpers ----------------------------------------------------
__device__ __forceinline__ void h8_to_f8(uint4 u, float4* dst) {
    __half2* h = (__half2*)&u;
    float2 f0 = __half22float2(h[0]), f1 = __half22float2(h[1]);
    float2 f2 = __half22float2(h[2]), f3 = __half22float2(h[3]);
    dst[0] = make_float4(f0.x, f0.y, f1.x, f1.y);
    dst[1] = make_float4(f2.x, f2.y, f3.x, f3.y);
}
__device__ __forceinline__ uint4 f8_to_h8(float4 a, float4 b) {
    uint4 u;
    ((__half2*)&u)[0] = __floats2half2_rn(a.x, a.y);
    ((__half2*)&u)[1] = __floats2half2_rn(a.z, a.w);
    ((__half2*)&u)[2] = __floats2half2_rn(b.x, b.y);
    ((__half2*)&u)[3] = __floats2half2_rn(b.z, b.w);
    return u;
}
__device__ __forceinline__ uint32_t pack_h2(float a, float b) {
    __half2 h = __floats2half2_rn(a, b);
    return *(uint32_t*)&h;
}

// ---------------- all-weights conversion fp32 -> fp16 (one launch) ----------------
__global__ void convertw_all(const float* __restrict__ inw, const float* __restrict__ ow,
                             const float* __restrict__ l1w, const float* __restrict__ l2w,
                             __half* __restrict__ o)
{
    GRID_DEP_SYNC();
    int i = blockIdx.x * 256 + threadIdx.x;   // grid = W_TOT/256
    float v;
    if      (i < W_OW) v = inw[i];
    else if (i < W_L1) v = ow [i - W_OW];
    else if (i < W_L2) v = l1w[i - W_L1];
    else               v = l2w[i - W_L2];
    o[i] = __float2half_rn(v);
}

// ---------------- rel position MLP (256 blocks — NOT fused into pos!) -------------
__global__ void rel_kernel(const float* __restrict__ w1, const float* __restrict__ b1,
                           const float* __restrict__ w2, const float* __restrict__ b2)
{
    GRID_DEP_SYNC();
    __shared__ float hid[64];
    int t = blockIdx.x;
    float cy = (float)(t / WS) / (float)(WS - 1);
    float cx = (float)(t % WS) / (float)(WS - 1);
    if (threadIdx.x < 64) {
        float h = cy * w1[threadIdx.x*2+0] + cx * w1[threadIdx.x*2+1] + b1[threadIdx.x];
        hid[threadIdx.x] = fmaxf(h, 0.f);
    }
    __syncthreads();
    int c = threadIdx.x;
    float s = b2[c];
    #pragma unroll 8
    for (int j = 0; j < 64; j++) s += hid[j] * w2[c*64 + j];
    g_rel[t*CC + c] = s;
}

// ---------------- pos[w,t,c] = glob_pos windowed + rel[t,c] ---------------------
__global__ void pos_kernel(const float* __restrict__ gp)
{
    GRID_DEP_SYNC();
    int idx = blockIdx.x * blockDim.x + threadIdx.x;
    if (idx >= NW*TT*CC) return;
    int c = idx % CC;
    int t = (idx / CC) % TT;
    int w = idx / (CC*TT);
    int wy = w / NWW, wx = w % NWW, ty = t / WS, tx = t % WS;
    g_pos[idx] = gp[(c*HH + wy*WS + ty)*WW + wx*WS + tx] + g_rel[t*CC + c];
}

// ---------------- valid[b,w] = maxpool(defe window) > 0 -------------------------
__global__ void valid_kernel(const float* __restrict__ defe)
{
    GRID_DEP_SYNC();
    int bw = blockIdx.x;
    int b = bw / NW, w = bw % NW;
    int t = threadIdx.x;
    int wy = w / NWW, wx = w % NWW, ty = t / WS, tx = t % WS;
    float v = defe[(b*HH + wy*WS + ty)*WW + wx*WS + tx];
    __shared__ float red[256];
    red[t] = v; __syncthreads();
    for (int s = 128; s > 0; s >>= 1) {
        if (t < s) red[t] = fmaxf(red[t], red[t+s]);
        __syncthreads();
    }
    if (t == 0) g_valid[bw] = red[0] > 0.f ? 1.f : 0.f;
}

// ---------------- window partition (tiled transpose), valid windows only ----------
__global__ void partition_kernel(const float* __restrict__ bm)
{
    GRID_DEP_SYNC();
    __shared__ float tile[32][33];
    int xt = blockIdx.x, y = blockIdx.y;
    int b = blockIdx.z >> 3, ct = blockIdx.z & 7;
    int c0 = ct * 32, x0 = xt * 32;
    int wy = y >> 4;
    int wA = wy*8 + (x0 >> 4), wB = wy*8 + ((x0+16) >> 4);
    if (g_valid[b*NW + wA] == 0.f && g_valid[b*NW + wB] == 0.f) return;
    int ci = threadIdx.x >> 5, xi = threadIdx.x & 31;
    #pragma unroll
    for (int p = 0; p < 4; p++) {
        int c = ci + p*8;
        tile[c][xi] = bm[((size_t)(b*CC + c0 + c)*HH + y)*WW + x0 + xi];
    }
    __syncthreads();
    int ty = y & 15;
    #pragma unroll
    for (int p = 0; p < 4; p++) {
        int xj = ci + p*8;
        int x = x0 + xj;
        int w = wy*8 + (x >> 4);
        if (g_valid[b*NW + w] == 0.f) continue;
        int t = ty*16 + (x & 15);
        float v = tile[xi][xj];
        size_t tok = (size_t)(b*NW + w)*TT + t;
        size_t idx = tok*CC + c0 + xi;
        g_x  [idx] = v;
        g_xh [idx] = __float2half_rn(v);
        g_xph[idx] = __float2half_rn(v + g_pos[((size_t)w*TT + t)*CC + c0 + xi]);
    }
}

// ================= FP16 tensor-core GEMM (3-stage cp.async, BK=64) ===============
// Block 128x128, 4 warps (2m x 2n), warp tile 64x64. 2 CTAs/SM. Early-exit invalid.

__device__ __forceinline__ void mma_f16(float c[4], const uint32_t a[4], const uint32_t b[2]) {
    asm volatile(
        "mma.sync.aligned.m16n8k16.row.col.f32.f16.f16.f32 "
        "{%0,%1,%2,%3}, {%4,%5,%6,%7}, {%8,%9}, {%0,%1,%2,%3};"
        : "+f"(c[0]), "+f"(c[1]), "+f"(c[2]), "+f"(c[3])
        : "r"(a[0]), "r"(a[1]), "r"(a[2]), "r"(a[3]), "r"(b[0]), "r"(b[1]));
}

__device__ __forceinline__ void cp_async16(uint32_t dst, const void* src) {
    asm volatile("cp.async.cg.shared.global [%0], [%1], 16;" :: "r"(dst), "l"(src));
}

__global__ __launch_bounds__(128)
void gemm_f16(const __half* __restrict__ A0, const __half* __restrict__ A1, int mswitch,
              const __half* __restrict__ Wt, const float* __restrict__ bias,
              __half* __restrict__ C, int ldC, int K, int relu,
              const float* __restrict__ vld)
{
    GRID_DEP_SYNC();
    int n0 = blockIdx.y << 7;
    if (vld[n0 >> 8] == 0.f) return;
    extern __shared__ char smc[];
    uint32_t asB = (uint32_t)__cvta_generic_to_shared(smc);
    uint32_t bsB = asB + 3*16384;
    int tid = threadIdx.x;
    int m0 = blockIdx.x << 7;
    const __half* A = (m0 < mswitch) ? A0 : A1;
    int warp = tid >> 5, lane = tid & 31;
    int wm = (warp & 1) << 6;
    int wn = (warp >> 1) << 6;
    int g = lane >> 2, q = lane & 3;

    int srow = tid >> 3;
    int scb  = tid & 7;

    float c[4][8][4] = {};
    int nk = K >> 6;

#define LOAD_STAGE(st, k0)                                                           \
    {                                                                                \
        _Pragma("unroll")                                                            \
        for (int p = 0; p < 8; p++) {                                                \
            int row = (p << 4) + srow;                                               \
            uint32_t sof = (st)*16384u + (row << 7) + ((scb ^ (row & 7)) << 4);      \
            cp_async16(asB + sof, A  + (size_t)(n0 + row) * K + (k0) + (scb << 3));  \
            cp_async16(bsB + sof, Wt + (size_t)(m0 + row) * K + (k0) + (scb << 3));  \
        }                                                                            \
        asm volatile("cp.async.commit_group;");                                      \
    }

    LOAD_STAGE(0, 0)
    if (nk > 1) LOAD_STAGE(1, 64)
    for (int kt = 0; kt < nk; kt++) {
        if (kt + 1 < nk) asm volatile("cp.async.wait_group 1;");
        else             asm volatile("cp.async.wait_group 0;");
        __syncthreads();
        if (kt + 2 < nk) {
            int st = (kt + 2) % 3;
            LOAD_STAGE(st, (kt + 2) << 6)
        }
        int cur = kt % 3;
        const uint32_t* Ac = (const uint32_t*)(smc + cur*16384);
        const uint32_t* Bc = (const uint32_t*)(smc + 3*16384 + cur*16384);
        #pragma unroll
        for (int kk = 0; kk < 4; kk++) {
            int ch0 = kk << 1, ch1 = ch0 + 1;
            uint32_t af[4][4];
            #pragma unroll
            for (int i = 0; i < 4; i++) {
                int r0 = wm + (i << 4) + g, r1 = r0 + 8;
                af[i][0] = Ac[(r0 << 5) + ((ch0 ^ (r0 & 7)) << 2) + q];
                af[i][1] = Ac[(r1 << 5) + ((ch0 ^ (r1 & 7)) << 2) + q];
                af[i][2] = Ac[(r0 << 5) + ((ch1 ^ (r0 & 7)) << 2) + q];
                af[i][3] = Ac[(r1 << 5) + ((ch1 ^ (r1 & 7)) << 2) + q];
            }
            uint32_t bf[8][2];
            #pragma unroll
            for (int j = 0; j < 8; j++) {
                int n = wn + (j << 3) + g;
                bf[j][0] = Bc[(n << 5) + ((ch0 ^ (n & 7)) << 2) + q];
                bf[j][1] = Bc[(n << 5) + ((ch1 ^ (n & 7)) << 2) + q];
            }
            #pragma unroll
            for (int i = 0; i < 4; i++)
                #pragma unroll
                for (int j = 0; j < 8; j++)
                    mma_f16(c[i][j], af[i], bf[j]);
        }
        __syncthreads();
    }
#undef LOAD_STAGE

    #pragma unroll
    for (int i = 0; i < 4; i++) {
        int row = n0 + wm + (i << 4) + g;
        #pragma unroll
        for (int j = 0; j < 8; j++) {
            int col = m0 + wn + (j << 3) + (q << 1);
            float b0 = bias[col], b1 = bias[col+1];
            float v0 = c[i][j][0] + b0, v1 = c[i][j][1] + b1;
            float v2 = c[i][j][2] + b0, v3 = c[i][j][3] + b1;
            if (relu) {
                v0 = fmaxf(v0, 0.f); v1 = fmaxf(v1, 0.f);
                v2 = fmaxf(v2, 0.f); v3 = fmaxf(v3, 0.f);
            }
            *(__half2*)&C[(size_t) row      * ldC + col] = __floats2half2_rn(v0, v1);
            *(__half2*)&C[(size_t)(row + 8) * ldC + col] = __floats2half2_rn(v2, v3);
        }
    }
}

// ================= within-window attention: flash-style MMA =======================
#define QSC (0.17677669529663687f * 1.4426950408889634f)

__global__ __launch_bounds__(256)
void attn_within_kernel(const __half* __restrict__ qkv, __half* __restrict__ gatt,
                        const float* __restrict__ vld)
{
    GRID_DEP_SYNC();
    int bw = blockIdx.x;
    if (vld[bw] == 0.f) return;
    __shared__ char sm[16384];   // Ks[2] @0 (64x32h, 64B rows); Vt[2] @8192 (32x64h, 128B rows)
    uint32_t sb = (uint32_t)__cvta_generic_to_shared(sm);
    int h = blockIdx.y;
    int tid = threadIdx.x;
    int warp = tid >> 5, lane = tid & 31;
    int g = lane >> 2, q = lane & 3;
    int wq0 = warp << 5;
    size_t base = (size_t)bw * TT;

    uint32_t aq[2][2][4];
    #pragma unroll
    for (int i = 0; i < 2; i++) {
        const __half* q0 = qkv + (base + wq0 + (i << 4) + g) * 768 + h * DH;
        const __half* q1 = q0 + 8 * 768;
        #pragma unroll
        for (int kk = 0; kk < 2; kk++) {
            aq[i][kk][0] = *(const uint32_t*)(q0 + (kk << 4) + (q << 1));
            aq[i][kk][1] = *(const uint32_t*)(q1 + (kk << 4) + (q << 1));
            aq[i][kk][2] = *(const uint32_t*)(q0 + (kk << 4) + 8 + (q << 1));
            aq[i][kk][3] = *(const uint32_t*)(q1 + (kk << 4) + 8 + (q << 1));
        }
    }

    float o[2][4][4] = {};
    float s[2][2] = {};

    int skey = tid >> 2, sch = tid & 3;

#define ATT_STAGE(b, kt)                                                              \
    {                                                                                 \
        const __half* kv = qkv + (base + ((kt) << 6) + skey) * 768 + h * DH;          \
        cp_async16(sb + (b)*4096u + (skey << 6) + ((sch ^ (skey & 3)) << 4),          \
                   kv + 256 + (sch << 3));                                            \
        asm volatile("cp.async.commit_group;");                                       \
        uint4 vv = *(const uint4*)(kv + 512 + (sch << 3));                            \
        const __half* vh = (const __half*)&vv;                                        \
        _Pragma("unroll")                                                             \
        for (int e = 0; e < 8; e++) {                                                 \
            int dh = (sch << 3) + e;                                                  \
            *(__half*)(sm + 8192 + (b)*4096 + (dh << 7)                               \
                       + (((skey >> 3) ^ (dh & 7)) << 4) + ((skey & 7) << 1)) = vh[e];\
        }                                                                             \
    }

    ATT_STAGE(0, 0)
    for (int kt = 0; kt < 4; kt++) {
        int buf = kt & 1;
        if (kt < 3) {
            ATT_STAGE(buf ^ 1, kt + 1)
            asm volatile("cp.async.wait_group 1;");
        } else {
            asm volatile("cp.async.wait_group 0;");
        }
        __syncthreads();

        float c[2][8][4] = {};
        const char* ks = sm + buf*4096;
        #pragma unroll
        for (int kk = 0; kk < 2; kk++) {
            int ch0 = kk << 1, ch1 = ch0 + 1;
            uint32_t bf[8][2];
            #pragma unroll
            for (int j = 0; j < 8; j++) {
                int n = (j << 3) + g;
                bf[j][0] = *(const uint32_t*)(ks + (n << 6) + ((ch0 ^ (n & 3)) << 4) + (q << 2));
                bf[j][1] = *(const uint32_t*)(ks + (n << 6) + ((ch1 ^ (n & 3)) << 4) + (q << 2));
            }
            #pragma unroll
            for (int i = 0; i < 2; i++)
                #pragma unroll
                for (int j = 0; j < 8; j++)
                    mma_f16(c[i][j], aq[i][kk], bf[j]);
        }

        #pragma unroll
        for (int i = 0; i < 2; i++)
            #pragma unroll
            for (int j = 0; j < 8; j++) {
                float p0 = exp2f(c[i][j][0] * QSC);
                float p1 = exp2f(c[i][j][1] * QSC);
                float p2 = exp2f(c[i][j][2] * QSC);
                float p3 = exp2f(c[i][j][3] * QSC);
                c[i][j][0] = p0; c[i][j][1] = p1; c[i][j][2] = p2; c[i][j][3] = p3;
                s[i][0] += p0 + p1;
                s[i][1] += p2 + p3;
            }

        const char* vt = sm + 8192 + buf*4096;
        #pragma unroll
        for (int kk = 0; kk < 4; kk++) {
            int ch0 = kk << 1, ch1 = ch0 + 1;
            uint32_t bv[4][2];
            #pragma unroll
            for (int j2 = 0; j2 < 4; j2++) {
                int n = (j2 << 3) + g;
                bv[j2][0] = *(const uint32_t*)(vt + (n << 7) + ((ch0 ^ (n & 7)) << 4) + (q << 2));
                bv[j2][1] = *(const uint32_t*)(vt + (n << 7) + ((ch1 ^ (n & 7)) << 4) + (q << 2));
            }
            #pragma unroll
            for (int i = 0; i < 2; i++) {
                uint32_t a[4];
                a[0] = pack_h2(c[i][2*kk  ][0], c[i][2*kk  ][1]);
                a[1] = pack_h2(c[i][2*kk  ][2], c[i][2*kk  ][3]);
                a[2] = pack_h2(c[i][2*kk+1][0], c[i][2*kk+1][1]);
                a[3] = pack_h2(c[i][2*kk+1][2], c[i][2*kk+1][3]);
                #pragma unroll
                for (int j2 = 0; j2 < 4; j2++)
                    mma_f16(o[i][j2], a, bv[j2]);
            }
        }
        __syncthreads();
    }
#undef ATT_STAGE

    #pragma unroll
    for (int i = 0; i < 2; i++) {
        #pragma unroll
        for (int hf = 0; hf < 2; hf++) {
            s[i][hf] += __shfl_xor_sync(0xffffffffu, s[i][hf], 1);
            s[i][hf] += __shfl_xor_sync(0xffffffffu, s[i][hf], 2);
        }
        float inv0 = s[i][0] > 0.f ? 1.f / s[i][0] : 0.f;
        float inv1 = s[i][1] > 0.f ? 1.f / s[i][1] : 0.f;
        size_t row = base + wq0 + (i << 4) + g;
        #pragma unroll
        for (int j2 = 0; j2 < 4; j2++) {
            int col = h * DH + (j2 << 3) + (q << 1);
            *(__half2*)(gatt + row*CC + col) =
                __floats2half2_rn(o[i][j2][0] * inv0, o[i][j2][1] * inv0);
            *(__half2*)(gatt + (row + 8)*CC + col) =
                __floats2half2_rn(o[i][j2][2] * inv1, o[i][j2][3] * inv1);
        }
    }
}

// ---------------- cross-window attention (key padding mask) ----------------------
__global__ void attn_cross_kernel(const __half* __restrict__ qkv,
                                  const float* __restrict__ gvalid,
                                  __half* __restrict__ gatt)
{
    GRID_DEP_SYNC();
    __shared__ float4 ks[NW*8];
    __shared__ float4 vs[NW*8];
    __shared__ float mk[NW];
    int bt = blockIdx.x;
    int b = bt / TT, t = bt % TT;
    int h = blockIdx.y;
    int wq = threadIdx.x;
    if (threadIdx.x < NW) mk[threadIdx.x] = gvalid[b*NW + threadIdx.x];
    __syncthreads();
    for (int i = threadIdx.x; i < NW*4; i += 64) {
        int w = i >> 2, d = i & 3;
        if (mk[w] == 0.f) continue;
        const __half* rb = qkv + ((size_t)(b*NW + w)*TT + t)*768 + h*DH;
        h8_to_f8(*(const uint4*)(rb + 256 + d*8), &ks[w*8 + d*2]);
        h8_to_f8(*(const uint4*)(rb + 512 + d*8), &vs[w*8 + d*2]);
    }
    __syncthreads();
    if (mk[wq] == 0.f) return;
    float4 qr[8];
    size_t qtok = (size_t)(b*NW + wq)*TT + t;
    const __half* qp = qkv + qtok*768 + h*DH;
    #pragma unroll
    for (int j = 0; j < 4; j++) h8_to_f8(*(const uint4*)(qp + j*8), &qr[j*2]);
    #pragma unroll
    for (int j = 0; j < 8; j++) {
        qr[j].x *= QSC; qr[j].y *= QSC; qr[j].z *= QSC; qr[j].w *= QSC;
    }
    float s = 0.f;
    float4 acc[8] = {};
    for (int i = 0; i < NW; i++) {
        if (mk[i] == 0.f) continue;
        const float4* kp = &ks[i*8];
        float sc = 0.f;
        #pragma unroll
        for (int j = 0; j < 8; j++) {
            float4 k4 = kp[j];
            sc = fmaf(qr[j].x, k4.x, sc); sc = fmaf(qr[j].y, k4.y, sc);
            sc = fmaf(qr[j].z, k4.z, sc); sc = fmaf(qr[j].w, k4.w, sc);
        }
        float e = exp2f(sc);
        s += e;
        const float4* vp = &vs[i*8];
        #pragma unroll
        for (int j = 0; j < 8; j++) {
            float4 v4 = vp[j];
            acc[j].x = fmaf(e, v4.x, acc[j].x); acc[j].y = fmaf(e, v4.y, acc[j].y);
            acc[j].z = fmaf(e, v4.z, acc[j].z); acc[j].w = fmaf(e, v4.w, acc[j].w);
        }
    }
    float inv = s > 0.f ? 1.f / s : 0.f;
    __half* op = gatt + qtok*CC + h*DH;
    #pragma unroll
    for (int j = 0; j < 4; j++) {
        float4 a = acc[2*j], b4 = acc[2*j+1];
        a.x *= inv; a.y *= inv; a.z *= inv; a.w *= inv;
        b4.x *= inv; b4.y *= inv; b4.z *= inv; b4.w *= inv;
        *(uint4*)(op + j*8) = f8_to_h8(a, b4);
    }
}

// ---------------- fused residual + LayerNorm (warp per token) --------------------
__global__ void ln_kernel(const float* __restrict__ a, const __half* __restrict__ r,
                          const float* __restrict__ g, const float* __restrict__ bb,
                          float* __restrict__ out, __half* __restrict__ out_h,
                          __half* __restrict__ out_hp, const float* __restrict__ vld)
{
    GRID_DEP_SYNC();
    if (vld[blockIdx.x >> 5] == 0.f) return;
    int warp = threadIdx.x >> 5, lane = threadIdx.x & 31;
    size_t tok = (size_t)blockIdx.x * 8 + warp;
    size_t base = tok * CC;
    float4 x0 = *(const float4*)(a + base + lane*4);
    float4 x1 = *(const float4*)(a + base + 128 + lane*4);
    uint2 ru0 = *(const uint2*)(r + base + lane*4);
    uint2 ru1 = *(const uint2*)(r + base + 128 + lane*4);
    float2 ra = __half22float2(*(__half2*)&ru0.x), rb2 = __half22float2(*(__half2*)&ru0.y);
    float2 rc = __half22float2(*(__half2*)&ru1.x), rd = __half22float2(*(__half2*)&ru1.y);
    x0.x += ra.x; x0.y += ra.y; x0.z += rb2.x; x0.w += rb2.y;
    x1.x += rc.x; x1.y += rc.y; x1.z += rd.x; x1.w += rd.y;
    float sum = x0.x+x0.y+x0.z+x0.w + x1.x+x1.y+x1.z+x1.w;
    float sq  = x0.x*x0.x+x0.y*x0.y+x0.z*x0.z+x0.w*x0.w
              + x1.x*x1.x+x1.y*x1.y+x1.z*x1.z+x1.w*x1.w;
    #pragma unroll
    for (int o = 16; o > 0; o >>= 1) {
        sum += __shfl_xor_sync(0xffffffffu, sum, o);
        sq  += __shfl_xor_sync(0xffffffffu, sq,  o);
    }
    float mu  = sum * (1.f/CC);
    float var = sq  * (1.f/CC) - mu*mu;
    float inv = rsqrtf(var + 1e-5f);
    float4 g0 = *(const float4*)(g  + lane*4);
    float4 g1 = *(const float4*)(g  + 128 + lane*4);
    float4 b0 = *(const float4*)(bb + lane*4);
    float4 b1 = *(const float4*)(bb + 128 + lane*4);
    float4 o0, o1;
    o0.x = (x0.x-mu)*inv*g0.x + b0.x; o0.y = (x0.y-mu)*inv*g0.y + b0.y;
    o0.z = (x0.z-mu)*inv*g0.z + b0.z; o0.w = (x0.w-mu)*inv*g0.w + b0.w;
    o1.x = (x1.x-mu)*inv*g1.x + b1.x; o1.y = (x1.y-mu)*inv*g1.y + b1.y;
    o1.z = (x1.z-mu)*inv*g1.z + b1.z; o1.w = (x1.w-mu)*inv*g1.w + b1.w;
    *(float4*)(out + base + lane*4)       = o0;
    *(float4*)(out + base + 128 + lane*4) = o1;
    if (out_h) {
        uint2 h0, h1;
        ((__half2*)&h0)[0] = __floats2half2_rn(o0.x, o0.y);
        ((__half2*)&h0)[1] = __floats2half2_rn(o0.z, o0.w);
        ((__half2*)&h1)[0] = __floats2half2_rn(o1.x, o1.y);
        ((__half2*)&h1)[1] = __floats2half2_rn(o1.z, o1.w);
        *(uint2*)(out_h + base + lane*4)       = h0;
        *(uint2*)(out_h + base + 128 + lane*4) = h1;
    }
    if (out_hp) {
        size_t pb = (tok & (NW*TT - 1)) * CC;
        float4 p0 = *(const float4*)(g_pos + pb + lane*4);
        float4 p1 = *(const float4*)(g_pos + pb + 128 + lane*4);
        uint2 h0, h1;
        ((__half2*)&h0)[0] = __floats2half2_rn(o0.x + p0.x, o0.y + p0.y);
        ((__half2*)&h0)[1] = __floats2half2_rn(o0.z + p0.z, o0.w + p0.w);
        ((__half2*)&h1)[0] = __floats2half2_rn(o1.x + p1.x, o1.y + p1.y);
        ((__half2*)&h1)[1] = __floats2half2_rn(o1.z + p1.z, o1.w + p1.w);
        *(uint2*)(out_hp + base + lane*4)       = h0;
        *(uint2*)(out_hp + base + 128 + lane*4) = h1;
    }
}

// ---------------- final scatter (tiled transpose): out = bm + x*valid ------------
__global__ void output_kernel(const float* __restrict__ bm, float* __restrict__ out)
{
    GRID_DEP_SYNC();
    __shared__ float tile[32][33];
    int xt = blockIdx.x, y = blockIdx.y;
    int b = blockIdx.z >> 3, ct = blockIdx.z & 7;
    int c0 = ct * 32, x0 = xt * 32;
    int wy = y >> 4, ty = y & 15;
    int hi = threadIdx.x >> 5, lane = threadIdx.x & 31;
    #pragma unroll
    for (int p = 0; p < 4; p++) {
        int xj = hi + p*8;
        int x = x0 + xj;
        int w = wy*8 + (x >> 4);
        int t = ty*16 + (x & 15);
        float vv = g_valid[b*NW + w];
        tile[xj][lane] = vv == 0.f ? 0.f
            : g_x[((size_t)(b*NW + w)*TT + t)*CC + c0 + lane];
    }
    __syncthreads();
    #pragma unroll
    for (int p = 0; p < 4; p++) {
        int c = hi + p*8;
        size_t idx = ((size_t)(b*CC + c0 + c)*HH + y)*WW + x0 + lane;
        out[idx] = bm[idx] + tile[lane][c];
    }
}

__global__ void valid_out_kernel(float* __restrict__ out)
{
    GRID_DEP_SYNC();
    int i = threadIdx.x;
    out[(size_t)BB*CC*HH*WW + i] = g_valid[i];
}

// ---------------- PDL launch helper ------------------------------------------------
template <typename... ExpTypes, typename... ActTypes>
static inline void pdl_launch(dim3 grid, dim3 block, size_t smem,
                              void (*kernel)(ExpTypes...), ActTypes... args)
{
    cudaLaunchConfig_t cfg = {};
    cfg.gridDim = grid;
    cfg.blockDim = block;
    cfg.dynamicSmemBytes = smem;
    cfg.stream = 0;
    cudaLaunchAttribute at[1];
    at[0].id = cudaLaunchAttributeProgrammaticStreamSerialization;
    at[0].val.programmaticStreamSerializationAllowed = 1;
    cfg.attrs = at;
    cfg.numAttrs = 1;
    cudaLaunchKernelEx(&cfg, kernel, (ExpTypes)args...);
}

// =================================================================================
extern "C" void kernel_launch(void* const* d_in, const int* in_sizes, int n_in,
                              void* d_out, int out_size)
{
    float  *p_x, *p_src, *p_valid;
    __half *p_xh, *p_xph, *p_qkvh, *p_atth, *p_srch, *p_yh, *p_ffh, *p_w16;
    cudaGetSymbolAddress((void**)&p_x,    g_x);
    cudaGetSymbolAddress((void**)&p_src,  g_src);
    cudaGetSymbolAddress((void**)&p_valid, g_valid);
    cudaGetSymbolAddress((void**)&p_xh,   g_xh);
    cudaGetSymbolAddress((void**)&p_xph,  g_xph);
    cudaGetSymbolAddress((void**)&p_qkvh, g_qkvh);
    cudaGetSymbolAddress((void**)&p_atth, g_atth);
    cudaGetSymbolAddress((void**)&p_srch, g_srch);
    cudaGetSymbolAddress((void**)&p_yh,   g_yh);
    cudaGetSymbolAddress((void**)&p_ffh,  g_ffh);
    cudaGetSymbolAddress((void**)&p_w16,  g_w16);

    static int smem_set = 0;
    if (!smem_set) {
        cudaFuncSetAttribute(gemm_f16, cudaFuncAttributeMaxDynamicSharedMemorySize, 98304);
        smem_set = 1;
    }

    int sh = (n_in > 2 && in_sizes[2] == 1) ? 0 : -1;
    const float* bm    = (const float*)d_in[0];
    const float* defe  = (const float*)d_in[1];
    const float* gp    = (const float*)d_in[3+sh];
    const float* rw1   = (const float*)d_in[4+sh];
    const float* rb1   = (const float*)d_in[5+sh];
    const float* rw2   = (const float*)d_in[6+sh];
    const float* rb2   = (const float*)d_in[7+sh];
    const float* inw   = (const float*)d_in[8+sh];
    const float* inb   = (const float*)d_in[9+sh];
    const float* ow    = (const float*)d_in[10+sh];
    const float* ob    = (const float*)d_in[11+sh];
    const float* l1w   = (const float*)d_in[12+sh];
    const float* l1b   = (const float*)d_in[13+sh];
    const float* l2w   = (const float*)d_in[14+sh];
    const float* l2b   = (const float*)d_in[15+sh];
    const float* g1    = (const float*)d_in[16+sh];
    const float* b1    = (const float*)d_in[17+sh];
    const float* g2    = (const float*)d_in[18+sh];
    const float* b2    = (const float*)d_in[19+sh];

    // ---- prep ----
    pdl_launch(dim3(W_TOT/256), dim3(256), 0, convertw_all, inw, ow, l1w, l2w, p_w16);
    pdl_launch(dim3(TT), dim3(256), 0, rel_kernel, rw1, rb1, rw2, rb2);
    pdl_launch(dim3((NW*TT*CC + 255)/256), dim3(256), 0, pos_kernel, gp);
    pdl_launch(dim3(BB*NW), dim3(256), 0, valid_kernel, defe);
    pdl_launch(dim3(4, 128, 32), dim3(256), 0, partition_kernel, bm);

    dim3 gQKV(6, NTOK/128);
    dim3 gOP (2, NTOK/128);
    dim3 gFF1(8, NTOK/128);
    const size_t GSM = 98304;

    for (int stage = 0; stage < 2; stage++) {
        pdl_launch(gQKV, dim3(128), GSM, gemm_f16,
                   (const __half*)p_xph, (const __half*)p_xh, 512,
                   (const __half*)(p_w16 + W_INW), inb, p_qkvh, 768, (int)CC, 0,
                   (const float*)p_valid);
        if (stage == 0)
            pdl_launch(dim3(BB*NW, NHEAD), dim3(256), 0, attn_within_kernel,
                       (const __half*)p_qkvh, p_atth, (const float*)p_valid);
        else
            pdl_launch(dim3(BB*TT, NHEAD), dim3(64), 0, attn_cross_kernel,
                       (const __half*)p_qkvh, (const float*)p_valid, p_atth);
        pdl_launch(gOP, dim3(128), GSM, gemm_f16,
                   (const __half*)p_atth, (const __half*)p_atth, 0,
                   (const __half*)(p_w16 + W_OW), ob, p_yh, (int)CC, (int)CC, 0,
                   (const float*)p_valid);
        pdl_launch(dim3(NTOK/8), dim3(256), 0, ln_kernel,
                   (const float*)p_x, (const __half*)p_yh, g1, b1,
                   p_src, p_srch, (__half*)0, (const float*)p_valid);
        pdl_launch(gFF1, dim3(128), GSM, gemm_f16,
                   (const __half*)p_srch, (const __half*)p_srch, 0,
                   (const __half*)(p_w16 + W_L1), l1b, p_ffh, (int)DFF, (int)CC, 1,
                   (const float*)p_valid);
        pdl_launch(gOP, dim3(128), GSM, gemm_f16,
                   (const __half*)p_ffh, (const __half*)p_ffh, 0,
                   (const __half*)(p_w16 + W_L2), l2b, p_yh, (int)CC, (int)DFF, 0,
                   (const float*)p_valid);
        pdl_launch(dim3(NTOK/8), dim3(256), 0, ln_kernel,
                   (const float*)p_src, (const __half*)p_yh, g2, b2, p_x,
                   stage == 0 ? p_xh  : (__half*)0,
                   stage == 0 ? p_xph : (__half*)0, (const float*)p_valid);
    }

    // ---- output ----
    pdl_launch(dim3(4, 128, 32), dim3(256), 0, output_kernel, bm, (float*)d_out);
    if (out_size >= BB*CC*HH*WW + BB*NW)
        pdl_launch(dim3(1), dim3(BB*NW), 0, valid_out_kernel, (float*)d_out);
}